// round 9
// baseline (speedup 1.0000x reference)
#include <cuda_runtime.h>
#include <cuda_fp16.h>
#include <cstdint>

#define D_H      128
#define D_IN     64
#define N_U      100000
#define N_I      50000
#define NNZ_MAX  5000000
#define N_LAYERS 2
#define SLOPE_F  0.2f
#define EPS_F    1e-5f
#define CHUNK    1024
#define WPITCH   136   // padded pitch (halfs) for ldmatrix conflict-free rows
#define VQ_SCALE 32767.f
#define VQ_INV   (1.f / 32767.f)

// ---------------- scratch (static device globals) ---------------------------
__device__ __align__(256) __half g_hU [(size_t)N_U * D_H];  // user features fp16
__device__ __align__(256) __half g_hI [(size_t)N_I * D_H];  // item features fp16
__device__ __align__(256) __half g_xhU[(size_t)N_U * D_H];  // spmm phase1 out fp16
__device__ __align__(256) __half g_xhI[(size_t)N_I * D_H];
__device__ __align__(256) __half g_lU [(size_t)N_U * D_H];  // lat1 fp16
__device__ __align__(256) __half g_lI [(size_t)N_I * D_H];
__device__ __align__(256) __half g_Wt [4][WPITCH * D_H];    // fp16 W^T, padded: [k][j]

// packed edge: bits [15..31] = partner index (17 bits), bits [0..14] = val q15
__device__ __align__(256) unsigned g_edgeU[NNZ_MAX];
__device__ __align__(256) unsigned g_edgeI[NNZ_MAX];
__device__ int g_ptrU[N_U + 1];
__device__ int g_ptrI[N_I + 1];
__device__ int g_posU[N_U];
__device__ int g_posI[N_I];
__device__ int g_cntU[N_U];
__device__ int g_cntI[N_I];
__device__ int g_chunkU[(N_U + CHUNK - 1) / CHUNK];
__device__ int g_chunkI[(N_I + CHUNK - 1) / CHUNK];

__device__ __forceinline__ float leakyf(float x) { return x > 0.f ? x : SLOPE_F * x; }

__device__ __forceinline__ unsigned pack_edge(int idx, float v) {
    int q = (int)(v * VQ_SCALE + 0.5f);
    q = q < 0 ? 0 : (q > 32767 ? 32767 : q);
    return ((unsigned)idx << 15) | (unsigned)q;
}

// ---------------- CSR build ---------------------------------------------------
__global__ void zero_int2arr(int* __restrict__ a, int na, int* __restrict__ b, int nb) {
    int i = blockIdx.x * blockDim.x + threadIdx.x;
    int stride = gridDim.x * blockDim.x;
    for (; i < na; i += stride) a[i] = 0;
    for (i = blockIdx.x * blockDim.x + threadIdx.x; i < nb; i += stride) b[i] = 0;
}

// ---------------- FC + LeakyReLU (job form, 128 threads/block) ----------------
__device__ __forceinline__ void fc_leaky_job(const float* __restrict__ emb,
                                             const float* __restrict__ W,   // [D_H, D_IN]
                                             const float* __restrict__ b,
                                             __half* __restrict__ outh,
                                             float*  __restrict__ outf,
                                             int nrows, int bid, int nblocks) {
    __shared__ float sWt[D_IN * D_H];
    __shared__ float sX[4][D_IN];
    const int j = threadIdx.x;
    for (int idx = j; idx < D_IN * D_H; idx += D_H) {
        int k = idx >> 7, jj = idx & 127;
        sWt[idx] = W[jj * D_IN + k];
    }
    const float bj = b[j];
    __syncthreads();

    for (int rbase = bid * 4; rbase < nrows; rbase += nblocks * 4) {
        for (int t = j; t < 4 * D_IN; t += D_H) {
            int rr = t >> 6, kk = t & 63;
            int row = rbase + rr;
            sX[rr][kk] = (row < nrows) ? emb[(size_t)row * D_IN + kk] : 0.f;
        }
        __syncthreads();
        float a0 = bj, a1 = bj, a2 = bj, a3 = bj;
        #pragma unroll 8
        for (int k = 0; k < D_IN; k++) {
            float w = sWt[k * D_H + j];
            a0 += w * sX[0][k];
            a1 += w * sX[1][k];
            a2 += w * sX[2][k];
            a3 += w * sX[3][k];
        }
        a0 = leakyf(a0); a1 = leakyf(a1); a2 = leakyf(a2); a3 = leakyf(a3);
        if (rbase + 0 < nrows) { outh[(size_t)(rbase+0)*D_H + j] = __float2half(a0); outf[(size_t)(rbase+0)*D_H + j] = a0; }
        if (rbase + 1 < nrows) { outh[(size_t)(rbase+1)*D_H + j] = __float2half(a1); outf[(size_t)(rbase+1)*D_H + j] = a1; }
        if (rbase + 2 < nrows) { outh[(size_t)(rbase+2)*D_H + j] = __float2half(a2); outf[(size_t)(rbase+2)*D_H + j] = a2; }
        if (rbase + 3 < nrows) { outh[(size_t)(rbase+3)*D_H + j] = __float2half(a3); outf[(size_t)(rbase+3)*D_H + j] = a3; }
        __syncthreads();
    }
}

// ---------------- fused prep: histogram || fc_u || fc_i ----------------------
#define HB 2048
#define FU 1024
#define FI 512
__global__ void prep_fused(const int* __restrict__ rows, const int* __restrict__ cols,
                           int* __restrict__ cntU, int* __restrict__ cntI, int nnz,
                           const float* __restrict__ emb,
                           const float* __restrict__ fc_u_w, const float* __restrict__ fc_u_b,
                           const float* __restrict__ fc_i_w, const float* __restrict__ fc_i_b,
                           __half* __restrict__ hU, __half* __restrict__ hI,
                           float* __restrict__ accU, float* __restrict__ accI) {
    const int bid = blockIdx.x;
    if (bid < HB) {
        int i = bid * 128 + threadIdx.x;
        int stride = HB * 128;
        for (; i < nnz; i += stride) {
            atomicAdd(&cntU[rows[i]], 1);
            atomicAdd(&cntI[cols[i]], 1);
        }
    } else if (bid < HB + FU) {
        fc_leaky_job(emb, fc_u_w, fc_u_b, hU, accU, N_U, bid - HB, FU);
    } else {
        fc_leaky_job(emb + (size_t)N_U * D_IN, fc_i_w, fc_i_b, hI, accI, N_I,
                     bid - HB - FU, FI);
    }
}

// scan phase 1 (dual): per-chunk sums
__global__ void scan_reduce_dual(const int* __restrict__ cntU, int* __restrict__ chU, int nchU,
                                 const int* __restrict__ cntI, int* __restrict__ chI) {
    __shared__ int sw[8];
    const int tid = threadIdx.x;
    const int* cnt;
    int* chunkSum;
    int n, cb;
    if ((int)blockIdx.x < nchU) { cnt = cntU; chunkSum = chU; n = N_U; cb = blockIdx.x; }
    else                        { cnt = cntI; chunkSum = chI; n = N_I; cb = blockIdx.x - nchU; }
    const int base = cb * CHUNK;
    int s = 0;
    #pragma unroll
    for (int t = 0; t < CHUNK / 256; t++) {
        int idx = base + t * 256 + tid;
        if (idx < n) s += cnt[idx];
    }
    #pragma unroll
    for (int off = 16; off; off >>= 1) s += __shfl_xor_sync(0xffffffffu, s, off);
    if ((tid & 31) == 0) sw[tid >> 5] = s;
    __syncthreads();
    if (tid == 0) {
        int tot = 0;
        #pragma unroll
        for (int w = 0; w < 8; w++) tot += sw[w];
        chunkSum[cb] = tot;
    }
}

// scan phase 2+3 fused: per-chunk scan; block computes its own chunk offset
__global__ void scan_write_dual(const int* __restrict__ cntU, const int* __restrict__ chU,
                                int* __restrict__ ptrU, int* __restrict__ posU, int nchU,
                                const int* __restrict__ cntI, const int* __restrict__ chI,
                                int* __restrict__ ptrI, int* __restrict__ posI) {
    __shared__ int sdata[CHUNK];
    __shared__ int sOff;
    const int tid = threadIdx.x;
    const int* cnt; const int* chunkSum;
    int* ptr; int* pos; int n, cb;
    if ((int)blockIdx.x < nchU) { cnt = cntU; chunkSum = chU; ptr = ptrU; pos = posU; n = N_U; cb = blockIdx.x; }
    else                        { cnt = cntI; chunkSum = chI; ptr = ptrI; pos = posI; n = N_I; cb = blockIdx.x - nchU; }
    if (tid < 32) {
        int s = 0;
        for (int c = tid; c < cb; c += 32) s += chunkSum[c];
        #pragma unroll
        for (int off = 16; off; off >>= 1) s += __shfl_xor_sync(0xffffffffu, s, off);
        if (tid == 0) sOff = s;
    }
    const int i = cb * CHUNK + tid;
    int v = (i < n) ? cnt[i] : 0;
    sdata[tid] = v;
    __syncthreads();
    #pragma unroll
    for (int off = 1; off < CHUNK; off <<= 1) {
        int t = (tid >= off) ? sdata[tid - off] : 0;
        __syncthreads();
        sdata[tid] += t;
        __syncthreads();
    }
    if (i < n) {
        int incl = sOff + sdata[tid];
        ptr[i + 1] = incl;
        pos[i] = incl - v;
    }
    if (i == 0) ptr[0] = 0;
}

__global__ void build_both_kernel(const int* __restrict__ rows,
                                  const int* __restrict__ cols,
                                  const float* __restrict__ vals,
                                  int* __restrict__ posU, int* __restrict__ posI,
                                  unsigned* __restrict__ edgeU, unsigned* __restrict__ edgeI,
                                  int nnz) {
    int i = blockIdx.x * blockDim.x + threadIdx.x;
    int stride = gridDim.x * blockDim.x;
    for (; i < nnz; i += stride) {
        int r = rows[i];
        int c = cols[i];
        float v = vals[i];
        unsigned pu_ = pack_edge(c, v);
        unsigned pi_ = pack_edge(r, v);
        int pa = atomicAdd(&posU[r], 1);
        edgeU[pa] = pu_;
        int qa = atomicAdd(&posI[c], 1);
        edgeI[qa] = pi_;
    }
}

// ---------------- W -> fp16 transposed (all 4 layer matrices, once) ----------
__global__ void wconvert_kernel(const float* __restrict__ Wu, const float* __restrict__ Wi) {
    int idx = blockIdx.x * blockDim.x + threadIdx.x;
    if (idx >= 4 * D_H * D_H) return;
    int slot = idx >> 14;
    int rem = idx & (D_H * D_H - 1);
    int k = rem >> 7, j = rem & 127;
    const float* W = (slot < 2) ? (Wu + (size_t)slot * D_H * D_H)
                                : (Wi + (size_t)(slot - 2) * D_H * D_H);
    g_Wt[slot][k * WPITCH + j] = __float2half(W[j * D_H + k]);
}

// ---------------- shared spmm accumulation core -------------------------------
// Packed edges: one 4B word/edge; one shuffle + local unpack per edge.
__device__ __forceinline__ void spmm_accum(const int* __restrict__ rowptr,
                                           const unsigned* __restrict__ edge,
                                           const __half* __restrict__ x,
                                           int row, int lane, int half16, int slot,
                                           float* a) {
    const int beg = rowptr[row];
    const int end = rowptr[row + 1];
    const uint4* __restrict__ x4 = reinterpret_cast<const uint4*>(x);
    #pragma unroll
    for (int q = 0; q < 8; q++) a[q] = 0.f;
    for (int base = beg; base < end; base += 32) {
        int e = base + lane;
        unsigned wv = 0;                 // idx=0, val=0 -> contributes nothing
        if (e < end) wv = __ldg(edge + e);
        int m = end - base; if (m > 32) m = 32;
        int mh = (m + 1) >> 1;
        for (int jj = 0; jj < mh; jj++) {
            int srcLane = 2 * jj + half16;
            unsigned wj = __shfl_sync(0xffffffffu, wv, srcLane);
            int   cj = (int)(wj >> 15);
            float vj = (float)(wj & 0x7FFFu) * VQ_INV;
            if (srcLane >= m) vj = 0.f;
            uint4 d = __ldg(x4 + (size_t)cj * 16 + slot);
            float2 f0 = __half22float2(*reinterpret_cast<__half2*>(&d.x));
            float2 f1 = __half22float2(*reinterpret_cast<__half2*>(&d.y));
            float2 f2 = __half22float2(*reinterpret_cast<__half2*>(&d.z));
            float2 f3 = __half22float2(*reinterpret_cast<__half2*>(&d.w));
            a[0] += vj * f0.x; a[1] += vj * f0.y;
            a[2] += vj * f1.x; a[3] += vj * f1.y;
            a[4] += vj * f2.x; a[5] += vj * f2.y;
            a[6] += vj * f3.x; a[7] += vj * f3.y;
        }
    }
    #pragma unroll
    for (int q = 0; q < 8; q++)
        a[q] += __shfl_xor_sync(0xffffffffu, a[q], 16);
}

// ---------------- phase-1 SpMM: fp16 output -----------------------------------
__device__ __forceinline__ void spmm_h_job(const int*  __restrict__ rowptr,
                                           const unsigned* __restrict__ edge,
                                           const __half* __restrict__ x,
                                           __half* __restrict__ yout,
                                           int nrows, int bid) {
    const int lane = threadIdx.x & 31;
    const int half16 = lane >> 4;
    const int slot = lane & 15;
    const int row  = bid * 8 + ((int)threadIdx.x >> 5);
    if (row >= nrows) return;
    float a[8];
    spmm_accum(rowptr, edge, x, row, lane, half16, slot, a);
    if (lane < 16) {
        __half2 h0 = __floats2half2_rn(a[0], a[1]);
        __half2 h1 = __floats2half2_rn(a[2], a[3]);
        __half2 h2 = __floats2half2_rn(a[4], a[5]);
        __half2 h3 = __floats2half2_rn(a[6], a[7]);
        uint4 o;
        o.x = *reinterpret_cast<unsigned int*>(&h0);
        o.y = *reinterpret_cast<unsigned int*>(&h1);
        o.z = *reinterpret_cast<unsigned int*>(&h2);
        o.w = *reinterpret_cast<unsigned int*>(&h3);
        reinterpret_cast<uint4*>(yout)[(size_t)row * 16 + slot] = o;
    }
}

__global__ void spmm_h_dual(const int*  __restrict__ ptrA, const unsigned* __restrict__ edgeA,
                            const __half* __restrict__ xA, __half* __restrict__ yA,
                            int nA, int blocksA,
                            const int*  __restrict__ ptrB, const unsigned* __restrict__ edgeB,
                            const __half* __restrict__ xB, __half* __restrict__ yB,
                            int nB) {
    if ((int)blockIdx.x < blocksA)
        spmm_h_job(ptrA, edgeA, xA, yA, nA, blockIdx.x);
    else
        spmm_h_job(ptrB, edgeB, xB, yB, nB, blockIdx.x - blocksA);
}

// ---------------- phase-3+4 fused: SpMM -> LN -> leaky -> feat+=, acc update --
__device__ __forceinline__ void spmm_ln_job(const int*  __restrict__ rowptr,
                                            const unsigned* __restrict__ edge,
                                            const __half* __restrict__ x,
                                            const float* __restrict__ g,
                                            const float* __restrict__ b,
                                            __half* __restrict__ feat,
                                            float* __restrict__ acc,
                                            int nrows, int bid, float oscale) {
    const int lane = threadIdx.x & 31;
    const int half16 = lane >> 4;
    const int slot = lane & 15;
    const int row  = bid * 8 + ((int)threadIdx.x >> 5);
    if (row >= nrows) return;
    float a[8];
    spmm_accum(rowptr, edge, x, row, lane, half16, slot, a);

    float s = 0.f, q = 0.f;
    #pragma unroll
    for (int t = 0; t < 8; t++) { s += a[t]; q += a[t] * a[t]; }
    #pragma unroll
    for (int off = 8; off; off >>= 1) {
        s += __shfl_xor_sync(0xffffffffu, s, off);
        q += __shfl_xor_sync(0xffffffffu, q, off);
    }
    const float inv = 1.f / (float)D_H;
    float mu = s * inv;
    float rs = rsqrtf(q * inv - mu * mu + EPS_F);

    if (lane < 16) {
        const float4 g0 = __ldg(reinterpret_cast<const float4*>(g) + 2 * slot);
        const float4 g1 = __ldg(reinterpret_cast<const float4*>(g) + 2 * slot + 1);
        const float4 b0 = __ldg(reinterpret_cast<const float4*>(b) + 2 * slot);
        const float4 b1 = __ldg(reinterpret_cast<const float4*>(b) + 2 * slot + 1);
        float h[8];
        h[0] = leakyf((a[0] - mu) * rs * g0.x + b0.x);
        h[1] = leakyf((a[1] - mu) * rs * g0.y + b0.y);
        h[2] = leakyf((a[2] - mu) * rs * g0.z + b0.z);
        h[3] = leakyf((a[3] - mu) * rs * g0.w + b0.w);
        h[4] = leakyf((a[4] - mu) * rs * g1.x + b1.x);
        h[5] = leakyf((a[5] - mu) * rs * g1.y + b1.y);
        h[6] = leakyf((a[6] - mu) * rs * g1.z + b1.z);
        h[7] = leakyf((a[7] - mu) * rs * g1.w + b1.w);
        uint4* fp = reinterpret_cast<uint4*>(feat) + (size_t)row * 16 + slot;
        uint4 fd = *fp;
        float2 f0 = __half22float2(*reinterpret_cast<__half2*>(&fd.x));
        float2 f1 = __half22float2(*reinterpret_cast<__half2*>(&fd.y));
        float2 f2 = __half22float2(*reinterpret_cast<__half2*>(&fd.z));
        float2 f3 = __half22float2(*reinterpret_cast<__half2*>(&fd.w));
        __half2 o0 = __floats2half2_rn(f0.x + h[0], f0.y + h[1]);
        __half2 o1 = __floats2half2_rn(f1.x + h[2], f1.y + h[3]);
        __half2 o2 = __floats2half2_rn(f2.x + h[4], f2.y + h[5]);
        __half2 o3 = __floats2half2_rn(f3.x + h[6], f3.y + h[7]);
        fd.x = *reinterpret_cast<unsigned int*>(&o0);
        fd.y = *reinterpret_cast<unsigned int*>(&o1);
        fd.z = *reinterpret_cast<unsigned int*>(&o2);
        fd.w = *reinterpret_cast<unsigned int*>(&o3);
        *fp = fd;
        float4* ap = reinterpret_cast<float4*>(acc) + (size_t)row * 32 + 2 * slot;
        float4 av0 = ap[0];
        float4 av1 = ap[1];
        av0.x = (av0.x + h[0]) * oscale;
        av0.y = (av0.y + h[1]) * oscale;
        av0.z = (av0.z + h[2]) * oscale;
        av0.w = (av0.w + h[3]) * oscale;
        av1.x = (av1.x + h[4]) * oscale;
        av1.y = (av1.y + h[5]) * oscale;
        av1.z = (av1.z + h[6]) * oscale;
        av1.w = (av1.w + h[7]) * oscale;
        ap[0] = av0;
        ap[1] = av1;
    }
}

__global__ void spmm_ln_dual(const int*  __restrict__ ptrA, const unsigned* __restrict__ edgeA,
                             const __half* __restrict__ xA,
                             const float* __restrict__ gA, const float* __restrict__ bA,
                             __half* __restrict__ featA, float* __restrict__ accA,
                             int nA, int blocksA,
                             const int*  __restrict__ ptrB, const unsigned* __restrict__ edgeB,
                             const __half* __restrict__ xB,
                             const float* __restrict__ gB, const float* __restrict__ bB,
                             __half* __restrict__ featB, float* __restrict__ accB,
                             int nB, float oscale) {
    if ((int)blockIdx.x < blocksA)
        spmm_ln_job(ptrA, edgeA, xA, gA, bA, featA, accA, nA, blockIdx.x, oscale);
    else
        spmm_ln_job(ptrB, edgeB, xB, gB, bB, featB, accB, nB, blockIdx.x - blocksA, oscale);
}

// ---------------- tensor-core GEMM (X @ W^T) + LayerNorm ---------------------
// Block: 128 threads (4 warps). M-tile = 16 rows; warp w owns cols [32w,32w+32).
__device__ __forceinline__ void gemm_ln_mma_job(const __half* __restrict__ X,
                                                const __half* __restrict__ Wt,
                                                const float* __restrict__ g,
                                                const float* __restrict__ b,
                                                __half* __restrict__ out,
                                                int nrows, int bid, int nblocks,
                                                __half* sW, __half* sX) {
    const int tid  = threadIdx.x;
    const int w    = tid >> 5;
    const int lane = tid & 31;

    __shared__ float sSum[16][4];
    __shared__ float sSq [16][4];
    __shared__ float sMu [16];
    __shared__ float sRs [16];

    {
        const uint4* src = reinterpret_cast<const uint4*>(Wt);
        uint4* dst = reinterpret_cast<uint4*>(sW);
        const int n16 = D_H * WPITCH / 8;
        for (int i = tid; i < n16; i += 128) dst[i] = src[i];
    }
    __syncthreads();

    unsigned int bfr[8][4][2];
    {
        unsigned int swBase = (unsigned int)__cvta_generic_to_shared(sW);
        #pragma unroll
        for (int kc = 0; kc < 8; kc++) {
            #pragma unroll
            for (int ncl = 0; ncl < 4; ncl++) {
                int krow = kc * 16 + (lane & 15);
                int col  = w * 32 + ncl * 8;
                unsigned int addr = swBase + (unsigned int)((krow * WPITCH + col) * 2);
                asm volatile("ldmatrix.sync.aligned.m8n8.x2.trans.shared.b16 {%0,%1}, [%2];"
                             : "=r"(bfr[kc][ncl][0]), "=r"(bfr[kc][ncl][1]) : "r"(addr));
            }
        }
    }

    float2 gv[4], bv[4];
    #pragma unroll
    for (int ncl = 0; ncl < 4; ncl++) {
        int j = w * 32 + ncl * 8 + (lane & 3) * 2;
        gv[ncl] = *reinterpret_cast<const float2*>(g + j);
        bv[ncl] = *reinterpret_cast<const float2*>(b + j);
    }

    const int ntiles = (nrows + 15) >> 4;
    unsigned int sxBase = (unsigned int)__cvta_generic_to_shared(sX);

    for (int tile = bid; tile < ntiles; tile += nblocks) {
        const int rowbase = tile * 16;
        {
            int r = tid >> 3;            // 0..15
            int p = tid & 7;             // 0..7, two uint4 chunks each
            int grow = rowbase + r;
            uint4 z = make_uint4(0, 0, 0, 0);
            const uint4* xr = reinterpret_cast<const uint4*>(X) + (size_t)grow * 16;
            uint4* dst = reinterpret_cast<uint4*>(sX + r * WPITCH);
            if (grow < nrows) {
                dst[p]     = __ldg(xr + p);
                dst[p + 8] = __ldg(xr + p + 8);
            } else {
                dst[p] = z; dst[p + 8] = z;
            }
        }
        __syncthreads();

        float acc[4][4];
        #pragma unroll
        for (int ncl = 0; ncl < 4; ncl++)
            #pragma unroll
            for (int q = 0; q < 4; q++) acc[ncl][q] = 0.f;

        #pragma unroll
        for (int kc = 0; kc < 8; kc++) {
            unsigned int a0, a1, a2, a3;
            int arow = (lane & 7) + ((lane >> 3) & 1) * 8;
            int acol = kc * 16 + ((lane >> 4) & 1) * 8;
            unsigned int addr = sxBase + (unsigned int)((arow * WPITCH + acol) * 2);
            asm volatile("ldmatrix.sync.aligned.m8n8.x4.shared.b16 {%0,%1,%2,%3}, [%4];"
                         : "=r"(a0), "=r"(a1), "=r"(a2), "=r"(a3) : "r"(addr));
            #pragma unroll
            for (int ncl = 0; ncl < 4; ncl++) {
                asm volatile("mma.sync.aligned.m16n8k16.row.col.f32.f16.f16.f32 "
                             "{%0,%1,%2,%3}, {%4,%5,%6,%7}, {%8,%9}, {%0,%1,%2,%3};"
                             : "+f"(acc[ncl][0]), "+f"(acc[ncl][1]),
                               "+f"(acc[ncl][2]), "+f"(acc[ncl][3])
                             : "r"(a0), "r"(a1), "r"(a2), "r"(a3),
                               "r"(bfr[kc][ncl][0]), "r"(bfr[kc][ncl][1]));
            }
        }

        float s0 = 0.f, s1 = 0.f, q0 = 0.f, q1 = 0.f;
        #pragma unroll
        for (int ncl = 0; ncl < 4; ncl++) {
            s0 += acc[ncl][0] + acc[ncl][1];
            s1 += acc[ncl][2] + acc[ncl][3];
            q0 += acc[ncl][0] * acc[ncl][0] + acc[ncl][1] * acc[ncl][1];
            q1 += acc[ncl][2] * acc[ncl][2] + acc[ncl][3] * acc[ncl][3];
        }
        s0 += __shfl_xor_sync(0xffffffffu, s0, 1);
        s0 += __shfl_xor_sync(0xffffffffu, s0, 2);
        s1 += __shfl_xor_sync(0xffffffffu, s1, 1);
        s1 += __shfl_xor_sync(0xffffffffu, s1, 2);
        q0 += __shfl_xor_sync(0xffffffffu, q0, 1);
        q0 += __shfl_xor_sync(0xffffffffu, q0, 2);
        q1 += __shfl_xor_sync(0xffffffffu, q1, 1);
        q1 += __shfl_xor_sync(0xffffffffu, q1, 2);
        if ((lane & 3) == 0) {
            int r = lane >> 2;
            sSum[r][w] = s0; sSum[r + 8][w] = s1;
            sSq [r][w] = q0; sSq [r + 8][w] = q1;
        }
        __syncthreads();
        if (tid < 16) {
            float s = sSum[tid][0] + sSum[tid][1] + sSum[tid][2] + sSum[tid][3];
            float q = sSq[tid][0] + sSq[tid][1] + sSq[tid][2] + sSq[tid][3];
            float mu = s * (1.f / 128.f);
            float var = q * (1.f / 128.f) - mu * mu;
            sMu[tid] = mu;
            sRs[tid] = rsqrtf(var + EPS_F);
        }
        __syncthreads();

        {
            int r0 = lane >> 2;
            float mu0 = sMu[r0],     rs0 = sRs[r0];
            float mu1 = sMu[r0 + 8], rs1 = sRs[r0 + 8];
            int grow0 = rowbase + r0;
            int grow1 = rowbase + r0 + 8;
            #pragma unroll
            for (int ncl = 0; ncl < 4; ncl++) {
                int j = w * 32 + ncl * 8 + (lane & 3) * 2;
                if (grow0 < nrows) {
                    __half2 o = __floats2half2_rn(
                        (acc[ncl][0] - mu0) * rs0 * gv[ncl].x + bv[ncl].x,
                        (acc[ncl][1] - mu0) * rs0 * gv[ncl].y + bv[ncl].y);
                    *reinterpret_cast<__half2*>(out + (size_t)grow0 * D_H + j) = o;
                }
                if (grow1 < nrows) {
                    __half2 o = __floats2half2_rn(
                        (acc[ncl][2] - mu1) * rs1 * gv[ncl].x + bv[ncl].x,
                        (acc[ncl][3] - mu1) * rs1 * gv[ncl].y + bv[ncl].y);
                    *reinterpret_cast<__half2*>(out + (size_t)grow1 * D_H + j) = o;
                }
            }
        }
        __syncthreads();
    }
}

__global__ void gemm_ln_mma_dual(const __half* __restrict__ XA, const __half* __restrict__ WtA,
                                 const float* __restrict__ gA, const float* __restrict__ bA,
                                 __half* __restrict__ outA, int nA, int blocksA,
                                 const __half* __restrict__ XB, const __half* __restrict__ WtB,
                                 const float* __restrict__ gB, const float* __restrict__ bB,
                                 __half* __restrict__ outB, int nB, int blocksB) {
    extern __shared__ __half smem[];
    __half* sW = smem;                       // D_H * WPITCH halfs
    __half* sX = smem + D_H * WPITCH;        // 16 * WPITCH halfs
    if ((int)blockIdx.x < blocksA)
        gemm_ln_mma_job(XA, WtA, gA, bA, outA, nA, blockIdx.x, blocksA, sW, sX);
    else
        gemm_ln_mma_job(XB, WtB, gB, bB, outB, nB, blockIdx.x - blocksA, blocksB, sW, sX);
}

// ---------------- launch ------------------------------------------------------
extern "C" void kernel_launch(void* const* d_in, const int* in_sizes, int n_in,
                              void* d_out, int out_size) {
    const float* emb     = (const float*)d_in[0];
    const float* fc_u_w  = (const float*)d_in[1];
    const float* fc_u_b  = (const float*)d_in[2];
    const float* fc_i_w  = (const float*)d_in[3];
    const float* fc_i_b  = (const float*)d_in[4];
    const float* vals    = (const float*)d_in[5];
    const float* Wu      = (const float*)d_in[6];
    const float* ln1g_u  = (const float*)d_in[7];
    const float* ln1b_u  = (const float*)d_in[8];
    const float* ln2g_u  = (const float*)d_in[9];
    const float* ln2b_u  = (const float*)d_in[10];
    const float* Wi      = (const float*)d_in[11];
    const float* ln1g_i  = (const float*)d_in[12];
    const float* ln1b_i  = (const float*)d_in[13];
    const float* ln2g_i  = (const float*)d_in[14];
    const float* ln2b_i  = (const float*)d_in[15];
    const int*   rows    = (const int*)d_in[16];
    const int*   cols    = (const int*)d_in[17];
    float* out = (float*)d_out;
    const int nnz = in_sizes[5];
    (void)n_in; (void)out_size;

    __half *hU, *hI, *xhU, *xhI, *lU, *lI, *Wt0;
    int *ptrU, *ptrI, *posU, *posI, *cntU, *cntI, *chU, *chI;
    unsigned *edgeU, *edgeI;
    cudaGetSymbolAddress((void**)&hU, g_hU);
    cudaGetSymbolAddress((void**)&hI, g_hI);
    cudaGetSymbolAddress((void**)&xhU, g_xhU);
    cudaGetSymbolAddress((void**)&xhI, g_xhI);
    cudaGetSymbolAddress((void**)&lU, g_lU);
    cudaGetSymbolAddress((void**)&lI, g_lI);
    cudaGetSymbolAddress((void**)&Wt0, g_Wt);
    cudaGetSymbolAddress((void**)&ptrU, g_ptrU);
    cudaGetSymbolAddress((void**)&ptrI, g_ptrI);
    cudaGetSymbolAddress((void**)&posU, g_posU);
    cudaGetSymbolAddress((void**)&posI, g_posI);
    cudaGetSymbolAddress((void**)&cntU, g_cntU);
    cudaGetSymbolAddress((void**)&cntI, g_cntI);
    cudaGetSymbolAddress((void**)&chU, g_chunkU);
    cudaGetSymbolAddress((void**)&chI, g_chunkI);
    cudaGetSymbolAddress((void**)&edgeU, g_edgeU);
    cudaGetSymbolAddress((void**)&edgeI, g_edgeI);

    const int EB = (nnz + 255) / 256;
    const int NCHU = (N_U + CHUNK - 1) / CHUNK;
    const int NCHI = (N_I + CHUNK - 1) / CHUNK;
    const size_t GEMM_SMEM = (size_t)(D_H + 16) * WPITCH * sizeof(__half);

    float* accU = out;
    float* accI = out + (size_t)N_U * D_H;

    // -------- prep: zero counters; then hist || fc_u || fc_i fused --------
    zero_int2arr<<<256, 256>>>(cntU, N_U, cntI, N_I);
    prep_fused<<<HB + FU + FI, 128>>>(rows, cols, cntU, cntI, nnz,
                                      emb, fc_u_w, fc_u_b, fc_i_w, fc_i_b,
                                      hU, hI, accU, accI);
    wconvert_kernel<<<(4 * D_H * D_H + 255) / 256, 256>>>(Wu, Wi);

    // -------- scan + build --------
    scan_reduce_dual<<<NCHU + NCHI, 256>>>(cntU, chU, NCHU, cntI, chI);
    scan_write_dual<<<NCHU + NCHI, CHUNK>>>(cntU, chU, ptrU, posU, NCHU,
                                            cntI, chI, ptrI, posI);
    build_both_kernel<<<EB, 256>>>(rows, cols, vals, posU, posI, edgeU, edgeI, nnz);

    const int SPU = (N_U + 7) / 8;
    const int SPI = (N_I + 7) / 8;
    const int GA = 512, GB = 1024;

    for (int k = 0; k < N_LAYERS; k++) {
        const __half* WtU_k = Wt0 + (size_t)k * WPITCH * D_H;
        const __half* WtI_k = Wt0 + (size_t)(2 + k) * WPITCH * D_H;
        const float oscale = (k == N_LAYERS - 1) ? (1.f / 3.f) : 1.f;

        // phase 1: xhI = A^T u  ||  xhU = A i   [fp16 out]
        spmm_h_dual<<<SPI + SPU, 256>>>(ptrI, edgeI, hU, xhI, N_I, SPI,
                                        ptrU, edgeU, hI, xhU, N_U);
        // phase 2: lI = LN(xhI Wu^T)  ||  lU = LN(xhU Wi^T)  [tensor cores]
        gemm_ln_mma_dual<<<GA + GB, 128, GEMM_SMEM>>>(
            xhI, WtU_k, ln1g_u + k * D_H, ln1b_u + k * D_H, lI, N_I, GA,
            xhU, WtI_k, ln1g_i + k * D_H, ln1b_i + k * D_H, lU, N_U, GB);
        // phase 3+4 fused: u-update from A lI  ||  i-update from A^T lU
        spmm_ln_dual<<<SPU + SPI, 256>>>(ptrU, edgeU, lI,
                                         ln2g_u + k * D_H, ln2b_u + k * D_H,
                                         hU, accU, N_U, SPU,
                                         ptrI, edgeI, lU,
                                         ln2g_i + k * D_H, ln2b_i + k * D_H,
                                         hI, accI, N_I, oscale);
    }
}

// round 10
// speedup vs baseline: 1.0140x; 1.0140x over previous
#include <cuda_runtime.h>
#include <cuda_fp16.h>
#include <cstdint>

#define D_H      128
#define D_IN     64
#define N_U      100000
#define N_I      50000
#define NNZ_MAX  5000000
#define N_LAYERS 2
#define SLOPE_F  0.2f
#define EPS_F    1e-5f
#define CHUNK    1024
#define WPITCH   136   // padded pitch (halfs) for ldmatrix conflict-free rows

// ---------------- scratch (static device globals) ---------------------------
__device__ __align__(256) __half g_hU [(size_t)N_U * D_H];  // user features fp16
__device__ __align__(256) __half g_hI [(size_t)N_I * D_H];  // item features fp16
__device__ __align__(256) __half g_xhU[(size_t)N_U * D_H];  // spmm phase1 out fp16
__device__ __align__(256) __half g_xhI[(size_t)N_I * D_H];
__device__ __align__(256) __half g_lU [(size_t)N_U * D_H];  // lat1 fp16
__device__ __align__(256) __half g_lI [(size_t)N_I * D_H];
__device__ __align__(256) __half g_Wt [4][WPITCH * D_H];    // fp16 W^T, padded: [k][j]

__device__ __align__(256) int2 g_edgeU[NNZ_MAX];
__device__ __align__(256) int2 g_edgeI[NNZ_MAX];
__device__ int g_ptrU[N_U + 1];
__device__ int g_ptrI[N_I + 1];
__device__ int g_posU[N_U];
__device__ int g_posI[N_I];
__device__ int g_cntU[N_U];
__device__ int g_cntI[N_I];
__device__ int g_chunkU[(N_U + CHUNK - 1) / CHUNK];
__device__ int g_chunkI[(N_I + CHUNK - 1) / CHUNK];

__device__ __forceinline__ float leakyf(float x) { return x > 0.f ? x : SLOPE_F * x; }

// ---------------- CSR build ---------------------------------------------------
__global__ void zero_int2arr(int* __restrict__ a, int na, int* __restrict__ b, int nb) {
    int i = blockIdx.x * blockDim.x + threadIdx.x;
    int stride = gridDim.x * blockDim.x;
    for (; i < na; i += stride) a[i] = 0;
    for (i = blockIdx.x * blockDim.x + threadIdx.x; i < nb; i += stride) b[i] = 0;
}

// ---------------- FC + LeakyReLU (job form, 128 threads/block) ----------------
__device__ __forceinline__ void fc_leaky_job(const float* __restrict__ emb,
                                             const float* __restrict__ W,   // [D_H, D_IN]
                                             const float* __restrict__ b,
                                             __half* __restrict__ outh,
                                             float*  __restrict__ outf,
                                             int nrows, int bid, int nblocks) {
    __shared__ float sWt[D_IN * D_H];
    __shared__ float sX[4][D_IN];
    const int j = threadIdx.x;
    for (int idx = j; idx < D_IN * D_H; idx += D_H) {
        int k = idx >> 7, jj = idx & 127;
        sWt[idx] = W[jj * D_IN + k];
    }
    const float bj = b[j];
    __syncthreads();

    for (int rbase = bid * 4; rbase < nrows; rbase += nblocks * 4) {
        for (int t = j; t < 4 * D_IN; t += D_H) {
            int rr = t >> 6, kk = t & 63;
            int row = rbase + rr;
            sX[rr][kk] = (row < nrows) ? emb[(size_t)row * D_IN + kk] : 0.f;
        }
        __syncthreads();
        float a0 = bj, a1 = bj, a2 = bj, a3 = bj;
        #pragma unroll 8
        for (int k = 0; k < D_IN; k++) {
            float w = sWt[k * D_H + j];
            a0 += w * sX[0][k];
            a1 += w * sX[1][k];
            a2 += w * sX[2][k];
            a3 += w * sX[3][k];
        }
        a0 = leakyf(a0); a1 = leakyf(a1); a2 = leakyf(a2); a3 = leakyf(a3);
        if (rbase + 0 < nrows) { outh[(size_t)(rbase+0)*D_H + j] = __float2half(a0); outf[(size_t)(rbase+0)*D_H + j] = a0; }
        if (rbase + 1 < nrows) { outh[(size_t)(rbase+1)*D_H + j] = __float2half(a1); outf[(size_t)(rbase+1)*D_H + j] = a1; }
        if (rbase + 2 < nrows) { outh[(size_t)(rbase+2)*D_H + j] = __float2half(a2); outf[(size_t)(rbase+2)*D_H + j] = a2; }
        if (rbase + 3 < nrows) { outh[(size_t)(rbase+3)*D_H + j] = __float2half(a3); outf[(size_t)(rbase+3)*D_H + j] = a3; }
        __syncthreads();
    }
}

// ---------------- fused prep: histogram || fc_u || fc_i || wconvert ----------
// blocks [0,HB): histogram; [HB,HB+FU): fc_u; [HB+FU,HB+FU+FI): fc_i;
// [HB+FU+FI, +WC): W fp16 transpose (4 layer matrices)
#define HB 2048
#define FU 1024
#define FI 512
#define WC 64
__global__ void prep_fused(const int* __restrict__ rows, const int* __restrict__ cols,
                           int* __restrict__ cntU, int* __restrict__ cntI, int nnz,
                           const float* __restrict__ emb,
                           const float* __restrict__ fc_u_w, const float* __restrict__ fc_u_b,
                           const float* __restrict__ fc_i_w, const float* __restrict__ fc_i_b,
                           __half* __restrict__ hU, __half* __restrict__ hI,
                           float* __restrict__ accU, float* __restrict__ accI,
                           const float* __restrict__ Wu, const float* __restrict__ Wi) {
    const int bid = blockIdx.x;
    if (bid < HB) {
        int i = bid * 128 + threadIdx.x;
        int stride = HB * 128;
        for (; i < nnz; i += stride) {
            atomicAdd(&cntU[rows[i]], 1);
            atomicAdd(&cntI[cols[i]], 1);
        }
    } else if (bid < HB + FU) {
        fc_leaky_job(emb, fc_u_w, fc_u_b, hU, accU, N_U, bid - HB, FU);
    } else if (bid < HB + FU + FI) {
        fc_leaky_job(emb + (size_t)N_U * D_IN, fc_i_w, fc_i_b, hI, accI, N_I,
                     bid - HB - FU, FI);
    } else {
        // W convert: 4*16384 elements over WC blocks of 128 threads (2 elems/thr/iter)
        int idx = (bid - HB - FU - FI) * 128 + threadIdx.x;
        const int total = 4 * D_H * D_H;
        for (; idx < total; idx += WC * 128) {
            int slot = idx >> 14;
            int rem = idx & (D_H * D_H - 1);
            int k = rem >> 7, j = rem & 127;
            const float* W = (slot < 2) ? (Wu + (size_t)slot * D_H * D_H)
                                        : (Wi + (size_t)(slot - 2) * D_H * D_H);
            g_Wt[slot][k * WPITCH + j] = __float2half(W[j * D_H + k]);
        }
    }
}

// scan phase 1 (dual): per-chunk sums
__global__ void scan_reduce_dual(const int* __restrict__ cntU, int* __restrict__ chU, int nchU,
                                 const int* __restrict__ cntI, int* __restrict__ chI) {
    __shared__ int sw[8];
    const int tid = threadIdx.x;
    const int* cnt;
    int* chunkSum;
    int n, cb;
    if ((int)blockIdx.x < nchU) { cnt = cntU; chunkSum = chU; n = N_U; cb = blockIdx.x; }
    else                        { cnt = cntI; chunkSum = chI; n = N_I; cb = blockIdx.x - nchU; }
    const int base = cb * CHUNK;
    int s = 0;
    #pragma unroll
    for (int t = 0; t < CHUNK / 256; t++) {
        int idx = base + t * 256 + tid;
        if (idx < n) s += cnt[idx];
    }
    #pragma unroll
    for (int off = 16; off; off >>= 1) s += __shfl_xor_sync(0xffffffffu, s, off);
    if ((tid & 31) == 0) sw[tid >> 5] = s;
    __syncthreads();
    if (tid == 0) {
        int tot = 0;
        #pragma unroll
        for (int w = 0; w < 8; w++) tot += sw[w];
        chunkSum[cb] = tot;
    }
}

__global__ void scan_offsets(int* __restrict__ cA, int nA, int* __restrict__ cB, int nB) {
    if (threadIdx.x == 0) {
        int acc = 0;
        for (int c = 0; c < nA; c++) { int v = cA[c]; cA[c] = acc; acc += v; }
    } else if (threadIdx.x == 32) {
        int acc = 0;
        for (int c = 0; c < nB; c++) { int v = cB[c]; cB[c] = acc; acc += v; }
    }
}

// scan phase 3 (dual): per-chunk inclusive scan + offset; write ptr and pos
__global__ void scan_write_dual(const int* __restrict__ cntU, const int* __restrict__ chU,
                                int* __restrict__ ptrU, int* __restrict__ posU, int nchU,
                                const int* __restrict__ cntI, const int* __restrict__ chI,
                                int* __restrict__ ptrI, int* __restrict__ posI) {
    __shared__ int sdata[CHUNK];
    const int tid = threadIdx.x;
    const int* cnt; const int* chunkOff;
    int* ptr; int* pos; int n, cb;
    if ((int)blockIdx.x < nchU) { cnt = cntU; chunkOff = chU; ptr = ptrU; pos = posU; n = N_U; cb = blockIdx.x; }
    else                        { cnt = cntI; chunkOff = chI; ptr = ptrI; pos = posI; n = N_I; cb = blockIdx.x - nchU; }
    const int i = cb * CHUNK + tid;
    int v = (i < n) ? cnt[i] : 0;
    sdata[tid] = v;
    __syncthreads();
    #pragma unroll
    for (int off = 1; off < CHUNK; off <<= 1) {
        int t = (tid >= off) ? sdata[tid - off] : 0;
        __syncthreads();
        sdata[tid] += t;
        __syncthreads();
    }
    if (i < n) {
        int off = chunkOff[cb];
        int incl = off + sdata[tid];
        ptr[i + 1] = incl;
        pos[i] = incl - v;
    }
    if (i == 0) ptr[0] = 0;
}

__global__ void build_both_kernel(const int* __restrict__ rows,
                                  const int* __restrict__ cols,
                                  const float* __restrict__ vals,
                                  int* __restrict__ posU, int* __restrict__ posI,
                                  int2* __restrict__ edgeU, int2* __restrict__ edgeI,
                                  int nnz) {
    int i = blockIdx.x * blockDim.x + threadIdx.x;
    int stride = gridDim.x * blockDim.x;
    for (; i < nnz; i += stride) {
        int r = rows[i];
        int c = cols[i];
        int v = __float_as_int(vals[i]);
        int pu_ = atomicAdd(&posU[r], 1);
        edgeU[pu_] = make_int2(c, v);
        int pi_ = atomicAdd(&posI[c], 1);
        edgeI[pi_] = make_int2(r, v);
    }
}

// ---------------- shared spmm accumulation core -------------------------------
__device__ __forceinline__ void spmm_accum(const int* __restrict__ rowptr,
                                           const int2* __restrict__ edge,
                                           const __half* __restrict__ x,
                                           int row, int lane, int half16, int slot,
                                           float* a) {
    const int beg = rowptr[row];
    const int end = rowptr[row + 1];
    const uint4* __restrict__ x4 = reinterpret_cast<const uint4*>(x);
    #pragma unroll
    for (int q = 0; q < 8; q++) a[q] = 0.f;
    for (int base = beg; base < end; base += 32) {
        int e = base + lane;
        int c = 0; float v = 0.f;
        if (e < end) {
            int2 ed = __ldg(edge + e);
            c = ed.x;
            v = __int_as_float(ed.y);
        }
        int m = end - base; if (m > 32) m = 32;
        int mh = (m + 1) >> 1;
        for (int jj = 0; jj < mh; jj++) {
            int srcLane = 2 * jj + half16;
            int   cj = __shfl_sync(0xffffffffu, c, srcLane);
            float vj = __shfl_sync(0xffffffffu, v, srcLane);
            if (srcLane >= m) vj = 0.f;
            uint4 d = __ldg(x4 + (size_t)cj * 16 + slot);
            float2 f0 = __half22float2(*reinterpret_cast<__half2*>(&d.x));
            float2 f1 = __half22float2(*reinterpret_cast<__half2*>(&d.y));
            float2 f2 = __half22float2(*reinterpret_cast<__half2*>(&d.z));
            float2 f3 = __half22float2(*reinterpret_cast<__half2*>(&d.w));
            a[0] += vj * f0.x; a[1] += vj * f0.y;
            a[2] += vj * f1.x; a[3] += vj * f1.y;
            a[4] += vj * f2.x; a[5] += vj * f2.y;
            a[6] += vj * f3.x; a[7] += vj * f3.y;
        }
    }
    #pragma unroll
    for (int q = 0; q < 8; q++)
        a[q] += __shfl_xor_sync(0xffffffffu, a[q], 16);
}

// ---------------- phase-1 SpMM: fp16 output -----------------------------------
__device__ __forceinline__ void spmm_h_job(const int*  __restrict__ rowptr,
                                           const int2* __restrict__ edge,
                                           const __half* __restrict__ x,
                                           __half* __restrict__ yout,
                                           int nrows, int bid) {
    const int lane = threadIdx.x & 31;
    const int half16 = lane >> 4;
    const int slot = lane & 15;
    const int row  = bid * 8 + ((int)threadIdx.x >> 5);
    if (row >= nrows) return;
    float a[8];
    spmm_accum(rowptr, edge, x, row, lane, half16, slot, a);
    if (lane < 16) {
        __half2 h0 = __floats2half2_rn(a[0], a[1]);
        __half2 h1 = __floats2half2_rn(a[2], a[3]);
        __half2 h2 = __floats2half2_rn(a[4], a[5]);
        __half2 h3 = __floats2half2_rn(a[6], a[7]);
        uint4 o;
        o.x = *reinterpret_cast<unsigned int*>(&h0);
        o.y = *reinterpret_cast<unsigned int*>(&h1);
        o.z = *reinterpret_cast<unsigned int*>(&h2);
        o.w = *reinterpret_cast<unsigned int*>(&h3);
        reinterpret_cast<uint4*>(yout)[(size_t)row * 16 + slot] = o;
    }
}

__global__ void spmm_h_dual(const int*  __restrict__ ptrA, const int2* __restrict__ edgeA,
                            const __half* __restrict__ xA, __half* __restrict__ yA,
                            int nA, int blocksA,
                            const int*  __restrict__ ptrB, const int2* __restrict__ edgeB,
                            const __half* __restrict__ xB, __half* __restrict__ yB,
                            int nB) {
    if ((int)blockIdx.x < blocksA)
        spmm_h_job(ptrA, edgeA, xA, yA, nA, blockIdx.x);
    else
        spmm_h_job(ptrB, edgeB, xB, yB, nB, blockIdx.x - blocksA);
}

// ---------------- phase-3+4 fused: SpMM -> LN -> leaky -> feat+=, acc update --
__device__ __forceinline__ void spmm_ln_job(const int*  __restrict__ rowptr,
                                            const int2* __restrict__ edge,
                                            const __half* __restrict__ x,
                                            const float* __restrict__ g,
                                            const float* __restrict__ b,
                                            __half* __restrict__ feat,
                                            float* __restrict__ acc,
                                            int nrows, int bid, float oscale) {
    const int lane = threadIdx.x & 31;
    const int half16 = lane >> 4;
    const int slot = lane & 15;
    const int row  = bid * 8 + ((int)threadIdx.x >> 5);
    if (row >= nrows) return;
    float a[8];
    spmm_accum(rowptr, edge, x, row, lane, half16, slot, a);

    float s = 0.f, q = 0.f;
    #pragma unroll
    for (int t = 0; t < 8; t++) { s += a[t]; q += a[t] * a[t]; }
    #pragma unroll
    for (int off = 8; off; off >>= 1) {
        s += __shfl_xor_sync(0xffffffffu, s, off);
        q += __shfl_xor_sync(0xffffffffu, q, off);
    }
    const float inv = 1.f / (float)D_H;
    float mu = s * inv;
    float rs = rsqrtf(q * inv - mu * mu + EPS_F);

    if (lane < 16) {
        const float4 g0 = __ldg(reinterpret_cast<const float4*>(g) + 2 * slot);
        const float4 g1 = __ldg(reinterpret_cast<const float4*>(g) + 2 * slot + 1);
        const float4 b0 = __ldg(reinterpret_cast<const float4*>(b) + 2 * slot);
        const float4 b1 = __ldg(reinterpret_cast<const float4*>(b) + 2 * slot + 1);
        float h[8];
        h[0] = leakyf((a[0] - mu) * rs * g0.x + b0.x);
        h[1] = leakyf((a[1] - mu) * rs * g0.y + b0.y);
        h[2] = leakyf((a[2] - mu) * rs * g0.z + b0.z);
        h[3] = leakyf((a[3] - mu) * rs * g0.w + b0.w);
        h[4] = leakyf((a[4] - mu) * rs * g1.x + b1.x);
        h[5] = leakyf((a[5] - mu) * rs * g1.y + b1.y);
        h[6] = leakyf((a[6] - mu) * rs * g1.z + b1.z);
        h[7] = leakyf((a[7] - mu) * rs * g1.w + b1.w);
        uint4* fp = reinterpret_cast<uint4*>(feat) + (size_t)row * 16 + slot;
        uint4 fd = *fp;
        float2 f0 = __half22float2(*reinterpret_cast<__half2*>(&fd.x));
        float2 f1 = __half22float2(*reinterpret_cast<__half2*>(&fd.y));
        float2 f2 = __half22float2(*reinterpret_cast<__half2*>(&fd.z));
        float2 f3 = __half22float2(*reinterpret_cast<__half2*>(&fd.w));
        __half2 o0 = __floats2half2_rn(f0.x + h[0], f0.y + h[1]);
        __half2 o1 = __floats2half2_rn(f1.x + h[2], f1.y + h[3]);
        __half2 o2 = __floats2half2_rn(f2.x + h[4], f2.y + h[5]);
        __half2 o3 = __floats2half2_rn(f3.x + h[6], f3.y + h[7]);
        fd.x = *reinterpret_cast<unsigned int*>(&o0);
        fd.y = *reinterpret_cast<unsigned int*>(&o1);
        fd.z = *reinterpret_cast<unsigned int*>(&o2);
        fd.w = *reinterpret_cast<unsigned int*>(&o3);
        *fp = fd;
        float4* ap = reinterpret_cast<float4*>(acc) + (size_t)row * 32 + 2 * slot;
        float4 av0 = ap[0];
        float4 av1 = ap[1];
        av0.x = (av0.x + h[0]) * oscale;
        av0.y = (av0.y + h[1]) * oscale;
        av0.z = (av0.z + h[2]) * oscale;
        av0.w = (av0.w + h[3]) * oscale;
        av1.x = (av1.x + h[4]) * oscale;
        av1.y = (av1.y + h[5]) * oscale;
        av1.z = (av1.z + h[6]) * oscale;
        av1.w = (av1.w + h[7]) * oscale;
        ap[0] = av0;
        ap[1] = av1;
    }
}

__global__ void spmm_ln_dual(const int*  __restrict__ ptrA, const int2* __restrict__ edgeA,
                             const __half* __restrict__ xA,
                             const float* __restrict__ gA, const float* __restrict__ bA,
                             __half* __restrict__ featA, float* __restrict__ accA,
                             int nA, int blocksA,
                             const int*  __restrict__ ptrB, const int2* __restrict__ edgeB,
                             const __half* __restrict__ xB,
                             const float* __restrict__ gB, const float* __restrict__ bB,
                             __half* __restrict__ featB, float* __restrict__ accB,
                             int nB, float oscale) {
    if ((int)blockIdx.x < blocksA)
        spmm_ln_job(ptrA, edgeA, xA, gA, bA, featA, accA, nA, blockIdx.x, oscale);
    else
        spmm_ln_job(ptrB, edgeB, xB, gB, bB, featB, accB, nB, blockIdx.x - blocksA, oscale);
}

// ---------------- tensor-core GEMM (X @ W^T) + LayerNorm ---------------------
// Block: 128 threads (4 warps). M-tile = 16 rows; warp w owns cols [32w,32w+32).
__device__ __forceinline__ void gemm_ln_mma_job(const __half* __restrict__ X,
                                                const __half* __restrict__ Wt,
                                                const float* __restrict__ g,
                                                const float* __restrict__ b,
                                                __half* __restrict__ out,
                                                int nrows, int bid, int nblocks,
                                                __half* sW, __half* sX) {
    const int tid  = threadIdx.x;
    const int w    = tid >> 5;
    const int lane = tid & 31;

    __shared__ float sSum[16][4];
    __shared__ float sSq [16][4];
    __shared__ float sMu [16];
    __shared__ float sRs [16];

    {
        const uint4* src = reinterpret_cast<const uint4*>(Wt);
        uint4* dst = reinterpret_cast<uint4*>(sW);
        const int n16 = D_H * WPITCH / 8;
        for (int i = tid; i < n16; i += 128) dst[i] = src[i];
    }
    __syncthreads();

    unsigned int bfr[8][4][2];
    {
        unsigned int swBase = (unsigned int)__cvta_generic_to_shared(sW);
        #pragma unroll
        for (int kc = 0; kc < 8; kc++) {
            #pragma unroll
            for (int ncl = 0; ncl < 4; ncl++) {
                int krow = kc * 16 + (lane & 15);
                int col  = w * 32 + ncl * 8;
                unsigned int addr = swBase + (unsigned int)((krow * WPITCH + col) * 2);
                asm volatile("ldmatrix.sync.aligned.m8n8.x2.trans.shared.b16 {%0,%1}, [%2];"
                             : "=r"(bfr[kc][ncl][0]), "=r"(bfr[kc][ncl][1]) : "r"(addr));
            }
        }
    }

    float2 gv[4], bv[4];
    #pragma unroll
    for (int ncl = 0; ncl < 4; ncl++) {
        int j = w * 32 + ncl * 8 + (lane & 3) * 2;
        gv[ncl] = *reinterpret_cast<const float2*>(g + j);
        bv[ncl] = *reinterpret_cast<const float2*>(b + j);
    }

    const int ntiles = (nrows + 15) >> 4;
    unsigned int sxBase = (unsigned int)__cvta_generic_to_shared(sX);

    for (int tile = bid; tile < ntiles; tile += nblocks) {
        const int rowbase = tile * 16;
        {
            int r = tid >> 3;            // 0..15
            int p = tid & 7;             // 0..7, two uint4 chunks each
            int grow = rowbase + r;
            uint4 z = make_uint4(0, 0, 0, 0);
            const uint4* xr = reinterpret_cast<const uint4*>(X) + (size_t)grow * 16;
            uint4* dst = reinterpret_cast<uint4*>(sX + r * WPITCH);
            if (grow < nrows) {
                dst[p]     = __ldg(xr + p);
                dst[p + 8] = __ldg(xr + p + 8);
            } else {
                dst[p] = z; dst[p + 8] = z;
            }
        }
        __syncthreads();

        float acc[4][4];
        #pragma unroll
        for (int ncl = 0; ncl < 4; ncl++)
            #pragma unroll
            for (int q = 0; q < 4; q++) acc[ncl][q] = 0.f;

        #pragma unroll
        for (int kc = 0; kc < 8; kc++) {
            unsigned int a0, a1, a2, a3;
            int arow = (lane & 7) + ((lane >> 3) & 1) * 8;
            int acol = kc * 16 + ((lane >> 4) & 1) * 8;
            unsigned int addr = sxBase + (unsigned int)((arow * WPITCH + acol) * 2);
            asm volatile("ldmatrix.sync.aligned.m8n8.x4.shared.b16 {%0,%1,%2,%3}, [%4];"
                         : "=r"(a0), "=r"(a1), "=r"(a2), "=r"(a3) : "r"(addr));
            #pragma unroll
            for (int ncl = 0; ncl < 4; ncl++) {
                asm volatile("mma.sync.aligned.m16n8k16.row.col.f32.f16.f16.f32 "
                             "{%0,%1,%2,%3}, {%4,%5,%6,%7}, {%8,%9}, {%0,%1,%2,%3};"
                             : "+f"(acc[ncl][0]), "+f"(acc[ncl][1]),
                               "+f"(acc[ncl][2]), "+f"(acc[ncl][3])
                             : "r"(a0), "r"(a1), "r"(a2), "r"(a3),
                               "r"(bfr[kc][ncl][0]), "r"(bfr[kc][ncl][1]));
            }
        }

        float s0 = 0.f, s1 = 0.f, q0 = 0.f, q1 = 0.f;
        #pragma unroll
        for (int ncl = 0; ncl < 4; ncl++) {
            s0 += acc[ncl][0] + acc[ncl][1];
            s1 += acc[ncl][2] + acc[ncl][3];
            q0 += acc[ncl][0] * acc[ncl][0] + acc[ncl][1] * acc[ncl][1];
            q1 += acc[ncl][2] * acc[ncl][2] + acc[ncl][3] * acc[ncl][3];
        }
        s0 += __shfl_xor_sync(0xffffffffu, s0, 1);
        s0 += __shfl_xor_sync(0xffffffffu, s0, 2);
        s1 += __shfl_xor_sync(0xffffffffu, s1, 1);
        s1 += __shfl_xor_sync(0xffffffffu, s1, 2);
        q0 += __shfl_xor_sync(0xffffffffu, q0, 1);
        q0 += __shfl_xor_sync(0xffffffffu, q0, 2);
        q1 += __shfl_xor_sync(0xffffffffu, q1, 1);
        q1 += __shfl_xor_sync(0xffffffffu, q1, 2);
        if ((lane & 3) == 0) {
            int r = lane >> 2;
            sSum[r][w] = s0; sSum[r + 8][w] = s1;
            sSq [r][w] = q0; sSq [r + 8][w] = q1;
        }
        __syncthreads();
        if (tid < 16) {
            float s = sSum[tid][0] + sSum[tid][1] + sSum[tid][2] + sSum[tid][3];
            float q = sSq[tid][0] + sSq[tid][1] + sSq[tid][2] + sSq[tid][3];
            float mu = s * (1.f / 128.f);
            float var = q * (1.f / 128.f) - mu * mu;
            sMu[tid] = mu;
            sRs[tid] = rsqrtf(var + EPS_F);
        }
        __syncthreads();

        {
            int r0 = lane >> 2;
            float mu0 = sMu[r0],     rs0 = sRs[r0];
            float mu1 = sMu[r0 + 8], rs1 = sRs[r0 + 8];
            int grow0 = rowbase + r0;
            int grow1 = rowbase + r0 + 8;
            #pragma unroll
            for (int ncl = 0; ncl < 4; ncl++) {
                int j = w * 32 + ncl * 8 + (lane & 3) * 2;
                if (grow0 < nrows) {
                    __half2 o = __floats2half2_rn(
                        (acc[ncl][0] - mu0) * rs0 * gv[ncl].x + bv[ncl].x,
                        (acc[ncl][1] - mu0) * rs0 * gv[ncl].y + bv[ncl].y);
                    *reinterpret_cast<__half2*>(out + (size_t)grow0 * D_H + j) = o;
                }
                if (grow1 < nrows) {
                    __half2 o = __floats2half2_rn(
                        (acc[ncl][2] - mu1) * rs1 * gv[ncl].x + bv[ncl].x,
                        (acc[ncl][3] - mu1) * rs1 * gv[ncl].y + bv[ncl].y);
                    *reinterpret_cast<__half2*>(out + (size_t)grow1 * D_H + j) = o;
                }
            }
        }
        __syncthreads();
    }
}

__global__ void gemm_ln_mma_dual(const __half* __restrict__ XA, const __half* __restrict__ WtA,
                                 const float* __restrict__ gA, const float* __restrict__ bA,
                                 __half* __restrict__ outA, int nA, int blocksA,
                                 const __half* __restrict__ XB, const __half* __restrict__ WtB,
                                 const float* __restrict__ gB, const float* __restrict__ bB,
                                 __half* __restrict__ outB, int nB, int blocksB) {
    extern __shared__ __half smem[];
    __half* sW = smem;                       // D_H * WPITCH halfs
    __half* sX = smem + D_H * WPITCH;        // 16 * WPITCH halfs
    if ((int)blockIdx.x < blocksA)
        gemm_ln_mma_job(XA, WtA, gA, bA, outA, nA, blockIdx.x, blocksA, sW, sX);
    else
        gemm_ln_mma_job(XB, WtB, gB, bB, outB, nB, blockIdx.x - blocksA, blocksB, sW, sX);
}

// ---------------- launch ------------------------------------------------------
extern "C" void kernel_launch(void* const* d_in, const int* in_sizes, int n_in,
                              void* d_out, int out_size) {
    const float* emb     = (const float*)d_in[0];
    const float* fc_u_w  = (const float*)d_in[1];
    const float* fc_u_b  = (const float*)d_in[2];
    const float* fc_i_w  = (const float*)d_in[3];
    const float* fc_i_b  = (const float*)d_in[4];
    const float* vals    = (const float*)d_in[5];
    const float* Wu      = (const float*)d_in[6];
    const float* ln1g_u  = (const float*)d_in[7];
    const float* ln1b_u  = (const float*)d_in[8];
    const float* ln2g_u  = (const float*)d_in[9];
    const float* ln2b_u  = (const float*)d_in[10];
    const float* Wi      = (const float*)d_in[11];
    const float* ln1g_i  = (const float*)d_in[12];
    const float* ln1b_i  = (const float*)d_in[13];
    const float* ln2g_i  = (const float*)d_in[14];
    const float* ln2b_i  = (const float*)d_in[15];
    const int*   rows    = (const int*)d_in[16];
    const int*   cols    = (const int*)d_in[17];
    float* out = (float*)d_out;
    const int nnz = in_sizes[5];
    (void)n_in; (void)out_size;

    __half *hU, *hI, *xhU, *xhI, *lU, *lI, *Wt0;
    int *ptrU, *ptrI, *posU, *posI, *cntU, *cntI, *chU, *chI;
    int2 *edgeU, *edgeI;
    cudaGetSymbolAddress((void**)&hU, g_hU);
    cudaGetSymbolAddress((void**)&hI, g_hI);
    cudaGetSymbolAddress((void**)&xhU, g_xhU);
    cudaGetSymbolAddress((void**)&xhI, g_xhI);
    cudaGetSymbolAddress((void**)&lU, g_lU);
    cudaGetSymbolAddress((void**)&lI, g_lI);
    cudaGetSymbolAddress((void**)&Wt0, g_Wt);
    cudaGetSymbolAddress((void**)&ptrU, g_ptrU);
    cudaGetSymbolAddress((void**)&ptrI, g_ptrI);
    cudaGetSymbolAddress((void**)&posU, g_posU);
    cudaGetSymbolAddress((void**)&posI, g_posI);
    cudaGetSymbolAddress((void**)&cntU, g_cntU);
    cudaGetSymbolAddress((void**)&cntI, g_cntI);
    cudaGetSymbolAddress((void**)&chU, g_chunkU);
    cudaGetSymbolAddress((void**)&chI, g_chunkI);
    cudaGetSymbolAddress((void**)&edgeU, g_edgeU);
    cudaGetSymbolAddress((void**)&edgeI, g_edgeI);

    const int EB = (nnz + 255) / 256;
    const int NCHU = (N_U + CHUNK - 1) / CHUNK;
    const int NCHI = (N_I + CHUNK - 1) / CHUNK;
    const size_t GEMM_SMEM = (size_t)(D_H + 16) * WPITCH * sizeof(__half);

    float* accU = out;
    float* accI = out + (size_t)N_U * D_H;

    // -------- prep: zero counters; then hist || fc_u || fc_i || wconvert -----
    zero_int2arr<<<256, 256>>>(cntU, N_U, cntI, N_I);
    prep_fused<<<HB + FU + FI + WC, 128>>>(rows, cols, cntU, cntI, nnz,
                                           emb, fc_u_w, fc_u_b, fc_i_w, fc_i_b,
                                           hU, hI, accU, accI, Wu, Wi);

    // -------- scan + build --------
    scan_reduce_dual<<<NCHU + NCHI, 256>>>(cntU, chU, NCHU, cntI, chI);
    scan_offsets<<<1, 64>>>(chU, NCHU, chI, NCHI);
    scan_write_dual<<<NCHU + NCHI, CHUNK>>>(cntU, chU, ptrU, posU, NCHU,
                                            cntI, chI, ptrI, posI);
    build_both_kernel<<<EB, 256>>>(rows, cols, vals, posU, posI, edgeU, edgeI, nnz);

    const int SPU = (N_U + 7) / 8;
    const int SPI = (N_I + 7) / 8;
    const int GA = 512, GB = 1024;

    for (int k = 0; k < N_LAYERS; k++) {
        const __half* WtU_k = Wt0 + (size_t)k * WPITCH * D_H;
        const __half* WtI_k = Wt0 + (size_t)(2 + k) * WPITCH * D_H;
        const float oscale = (k == N_LAYERS - 1) ? (1.f / 3.f) : 1.f;

        // phase 1: xhI = A^T u  ||  xhU = A i   [fp16 out]
        spmm_h_dual<<<SPI + SPU, 256>>>(ptrI, edgeI, hU, xhI, N_I, SPI,
                                        ptrU, edgeU, hI, xhU, N_U);
        // phase 2: lI = LN(xhI Wu^T)  ||  lU = LN(xhU Wi^T)  [tensor cores]
        gemm_ln_mma_dual<<<GA + GB, 128, GEMM_SMEM>>>(
            xhI, WtU_k, ln1g_u + k * D_H, ln1b_u + k * D_H, lI, N_I, GA,
            xhU, WtI_k, ln1g_i + k * D_H, ln1b_i + k * D_H, lU, N_U, GB);
        // phase 3+4 fused: u-update from A lI  ||  i-update from A^T lU
        spmm_ln_dual<<<SPU + SPI, 256>>>(ptrU, edgeU, lI,
                                         ln2g_u + k * D_H, ln2b_u + k * D_H,
                                         hU, accU, N_U, SPU,
                                         ptrI, edgeI, lU,
                                         ln2g_i + k * D_H, ln2b_i + k * D_H,
                                         hI, accI, N_I, oscale);
    }
}

// round 11
// speedup vs baseline: 1.1589x; 1.1429x over previous
#include <cuda_runtime.h>
#include <cuda_fp16.h>
#include <cstdint>

#define D_H      128
#define D_IN     64
#define N_U      100000
#define N_I      50000
#define NNZ_MAX  5000000
#define N_LAYERS 2
#define SLOPE_F  0.2f
#define EPS_F    1e-5f
#define CHUNK    1024
#define WPITCH   136   // padded pitch (halfs) for ldmatrix conflict-free rows

// ---------------- scratch (static device globals) ---------------------------
__device__ __align__(256) __half g_hU [(size_t)N_U * D_H];  // user features fp16
__device__ __align__(256) __half g_hI [(size_t)N_I * D_H];  // item features fp16
__device__ __align__(256) __half g_xhU[(size_t)N_U * D_H];  // spmm phase1 out fp16
__device__ __align__(256) __half g_xhI[(size_t)N_I * D_H];
__device__ __align__(256) __half g_lU [(size_t)N_U * D_H];  // lat1 fp16
__device__ __align__(256) __half g_lI [(size_t)N_I * D_H];
__device__ __align__(256) __half g_Wt [4][WPITCH * D_H];    // fp16 W^T, padded: [k][j]

__device__ __align__(256) int2 g_edgeU[NNZ_MAX];
__device__ __align__(256) int2 g_edgeI[NNZ_MAX];
__device__ int g_ptrU[N_U + 1];
__device__ int g_ptrI[N_I + 1];
__device__ int g_posU[N_U];
__device__ int g_posI[N_I];
__device__ int g_cntU[N_U];
__device__ int g_cntI[N_I];
__device__ int g_chunkU[(N_U + CHUNK - 1) / CHUNK];
__device__ int g_chunkI[(N_I + CHUNK - 1) / CHUNK];

__device__ __forceinline__ float leakyf(float x) { return x > 0.f ? x : SLOPE_F * x; }

// ---------------- CSR build ---------------------------------------------------
__global__ void zero_int2arr(int* __restrict__ a, int na, int* __restrict__ b, int nb) {
    int i = blockIdx.x * blockDim.x + threadIdx.x;
    int stride = gridDim.x * blockDim.x;
    for (; i < na; i += stride) a[i] = 0;
    for (i = blockIdx.x * blockDim.x + threadIdx.x; i < nb; i += stride) b[i] = 0;
}

// ---------------- FC + LeakyReLU (job form, 128 threads/block) ----------------
__device__ __forceinline__ void fc_leaky_job(const float* __restrict__ emb,
                                             const float* __restrict__ W,   // [D_H, D_IN]
                                             const float* __restrict__ b,
                                             __half* __restrict__ outh,
                                             float*  __restrict__ outf,
                                             int nrows, int bid, int nblocks) {
    __shared__ float sWt[D_IN * D_H];
    __shared__ float sX[4][D_IN];
    const int j = threadIdx.x;
    for (int idx = j; idx < D_IN * D_H; idx += D_H) {
        int k = idx >> 7, jj = idx & 127;
        sWt[idx] = W[jj * D_IN + k];
    }
    const float bj = b[j];
    __syncthreads();

    for (int rbase = bid * 4; rbase < nrows; rbase += nblocks * 4) {
        for (int t = j; t < 4 * D_IN; t += D_H) {
            int rr = t >> 6, kk = t & 63;
            int row = rbase + rr;
            sX[rr][kk] = (row < nrows) ? emb[(size_t)row * D_IN + kk] : 0.f;
        }
        __syncthreads();
        float a0 = bj, a1 = bj, a2 = bj, a3 = bj;
        #pragma unroll 8
        for (int k = 0; k < D_IN; k++) {
            float w = sWt[k * D_H + j];
            a0 += w * sX[0][k];
            a1 += w * sX[1][k];
            a2 += w * sX[2][k];
            a3 += w * sX[3][k];
        }
        a0 = leakyf(a0); a1 = leakyf(a1); a2 = leakyf(a2); a3 = leakyf(a3);
        if (rbase + 0 < nrows) { outh[(size_t)(rbase+0)*D_H + j] = __float2half(a0); outf[(size_t)(rbase+0)*D_H + j] = a0; }
        if (rbase + 1 < nrows) { outh[(size_t)(rbase+1)*D_H + j] = __float2half(a1); outf[(size_t)(rbase+1)*D_H + j] = a1; }
        if (rbase + 2 < nrows) { outh[(size_t)(rbase+2)*D_H + j] = __float2half(a2); outf[(size_t)(rbase+2)*D_H + j] = a2; }
        if (rbase + 3 < nrows) { outh[(size_t)(rbase+3)*D_H + j] = __float2half(a3); outf[(size_t)(rbase+3)*D_H + j] = a3; }
        __syncthreads();
    }
}

// ---------------- fused prep: histogram || fc_u || fc_i || wconvert ----------
#define HB 2048
#define FU 1024
#define FI 512
#define WC 64
__global__ void prep_fused(const int* __restrict__ rows, const int* __restrict__ cols,
                           int* __restrict__ cntU, int* __restrict__ cntI, int nnz,
                           const float* __restrict__ emb,
                           const float* __restrict__ fc_u_w, const float* __restrict__ fc_u_b,
                           const float* __restrict__ fc_i_w, const float* __restrict__ fc_i_b,
                           __half* __restrict__ hU, __half* __restrict__ hI,
                           float* __restrict__ accU, float* __restrict__ accI,
                           const float* __restrict__ Wu, const float* __restrict__ Wi) {
    const int bid = blockIdx.x;
    if (bid < HB) {
        int i = bid * 128 + threadIdx.x;
        int stride = HB * 128;
        for (; i < nnz; i += stride) {
            atomicAdd(&cntU[rows[i]], 1);
            atomicAdd(&cntI[cols[i]], 1);
        }
    } else if (bid < HB + FU) {
        fc_leaky_job(emb, fc_u_w, fc_u_b, hU, accU, N_U, bid - HB, FU);
    } else if (bid < HB + FU + FI) {
        fc_leaky_job(emb + (size_t)N_U * D_IN, fc_i_w, fc_i_b, hI, accI, N_I,
                     bid - HB - FU, FI);
    } else {
        int idx = (bid - HB - FU - FI) * 128 + threadIdx.x;
        const int total = 4 * D_H * D_H;
        for (; idx < total; idx += WC * 128) {
            int slot = idx >> 14;
            int rem = idx & (D_H * D_H - 1);
            int k = rem >> 7, j = rem & 127;
            const float* W = (slot < 2) ? (Wu + (size_t)slot * D_H * D_H)
                                        : (Wi + (size_t)(slot - 2) * D_H * D_H);
            g_Wt[slot][k * WPITCH + j] = __float2half(W[j * D_H + k]);
        }
    }
}

// scan phase 1 (dual): per-chunk sums
__global__ void scan_reduce_dual(const int* __restrict__ cntU, int* __restrict__ chU, int nchU,
                                 const int* __restrict__ cntI, int* __restrict__ chI) {
    __shared__ int sw[8];
    const int tid = threadIdx.x;
    const int* cnt;
    int* chunkSum;
    int n, cb;
    if ((int)blockIdx.x < nchU) { cnt = cntU; chunkSum = chU; n = N_U; cb = blockIdx.x; }
    else                        { cnt = cntI; chunkSum = chI; n = N_I; cb = blockIdx.x - nchU; }
    const int base = cb * CHUNK;
    int s = 0;
    #pragma unroll
    for (int t = 0; t < CHUNK / 256; t++) {
        int idx = base + t * 256 + tid;
        if (idx < n) s += cnt[idx];
    }
    #pragma unroll
    for (int off = 16; off; off >>= 1) s += __shfl_xor_sync(0xffffffffu, s, off);
    if ((tid & 31) == 0) sw[tid >> 5] = s;
    __syncthreads();
    if (tid == 0) {
        int tot = 0;
        #pragma unroll
        for (int w = 0; w < 8; w++) tot += sw[w];
        chunkSum[cb] = tot;
    }
}

// scan phase 2+3 fused: per-chunk scan; warp0 computes the chunk offset itself
__global__ void scan_write_dual(const int* __restrict__ cntU, const int* __restrict__ chU,
                                int* __restrict__ ptrU, int* __restrict__ posU, int nchU,
                                const int* __restrict__ cntI, const int* __restrict__ chI,
                                int* __restrict__ ptrI, int* __restrict__ posI) {
    __shared__ int sdata[CHUNK];
    __shared__ int sOff;
    const int tid = threadIdx.x;
    const int* cnt; const int* chunkSum;
    int* ptr; int* pos; int n, cb;
    if ((int)blockIdx.x < nchU) { cnt = cntU; chunkSum = chU; ptr = ptrU; pos = posU; n = N_U; cb = blockIdx.x; }
    else                        { cnt = cntI; chunkSum = chI; ptr = ptrI; pos = posI; n = N_I; cb = blockIdx.x - nchU; }
    if (tid < 32) {
        int s = 0;
        for (int c = tid; c < cb; c += 32) s += chunkSum[c];
        #pragma unroll
        for (int off = 16; off; off >>= 1) s += __shfl_xor_sync(0xffffffffu, s, off);
        if (tid == 0) sOff = s;
    }
    const int i = cb * CHUNK + tid;
    int v = (i < n) ? cnt[i] : 0;
    sdata[tid] = v;
    __syncthreads();
    #pragma unroll
    for (int off = 1; off < CHUNK; off <<= 1) {
        int t = (tid >= off) ? sdata[tid - off] : 0;
        __syncthreads();
        sdata[tid] += t;
        __syncthreads();
    }
    if (i < n) {
        int incl = sOff + sdata[tid];
        ptr[i + 1] = incl;
        pos[i] = incl - v;
    }
    if (i == 0) ptr[0] = 0;
}

__global__ void build_both_kernel(const int* __restrict__ rows,
                                  const int* __restrict__ cols,
                                  const float* __restrict__ vals,
                                  int* __restrict__ posU, int* __restrict__ posI,
                                  int2* __restrict__ edgeU, int2* __restrict__ edgeI,
                                  int nnz) {
    int i = blockIdx.x * blockDim.x + threadIdx.x;
    int stride = gridDim.x * blockDim.x;
    for (; i < nnz; i += stride) {
        int r = rows[i];
        int c = cols[i];
        int v = __float_as_int(vals[i]);
        int pu_ = atomicAdd(&posU[r], 1);
        edgeU[pu_] = make_int2(c, v);
        int pi_ = atomicAdd(&posI[c], 1);
        edgeI[pi_] = make_int2(r, v);
    }
}

// ---------------- shared spmm accumulation core -------------------------------
// 64-edge double-buffered batches: two edge-word loads per lane hoisted per
// outer iteration; inner loop split into two 16-pair halves for deeper MLP.
__device__ __forceinline__ void spmm_accum(const int* __restrict__ rowptr,
                                           const int2* __restrict__ edge,
                                           const __half* __restrict__ x,
                                           int row, int lane, int half16, int slot,
                                           float* a) {
    const int beg = rowptr[row];
    const int end = rowptr[row + 1];
    const uint4* __restrict__ x4 = reinterpret_cast<const uint4*>(x);
    #pragma unroll
    for (int q = 0; q < 8; q++) a[q] = 0.f;
    for (int base = beg; base < end; base += 64) {
        int eA = base + lane;
        int eB = base + 32 + lane;
        int cA = 0, cB = 0;
        float vA = 0.f, vB = 0.f;
        if (eA < end) { int2 ed = __ldg(edge + eA); cA = ed.x; vA = __int_as_float(ed.y); }
        if (eB < end) { int2 ed = __ldg(edge + eB); cB = ed.x; vB = __int_as_float(ed.y); }
        int m = end - base; if (m > 64) m = 64;
        // first 32 edges
        int m1 = m < 32 ? m : 32;
        int mh1 = (m1 + 1) >> 1;
        for (int jj = 0; jj < mh1; jj++) {
            int srcLane = 2 * jj + half16;
            int   cj = __shfl_sync(0xffffffffu, cA, srcLane);
            float vj = __shfl_sync(0xffffffffu, vA, srcLane);
            if (srcLane >= m1) vj = 0.f;
            uint4 d = __ldg(x4 + (size_t)cj * 16 + slot);
            float2 f0 = __half22float2(*reinterpret_cast<__half2*>(&d.x));
            float2 f1 = __half22float2(*reinterpret_cast<__half2*>(&d.y));
            float2 f2 = __half22float2(*reinterpret_cast<__half2*>(&d.z));
            float2 f3 = __half22float2(*reinterpret_cast<__half2*>(&d.w));
            a[0] += vj * f0.x; a[1] += vj * f0.y;
            a[2] += vj * f1.x; a[3] += vj * f1.y;
            a[4] += vj * f2.x; a[5] += vj * f2.y;
            a[6] += vj * f3.x; a[7] += vj * f3.y;
        }
        // second 32 edges
        int m2 = m - 32;
        if (m2 > 0) {
            int mh2 = (m2 + 1) >> 1;
            for (int jj = 0; jj < mh2; jj++) {
                int srcLane = 2 * jj + half16;
                int   cj = __shfl_sync(0xffffffffu, cB, srcLane);
                float vj = __shfl_sync(0xffffffffu, vB, srcLane);
                if (srcLane >= m2) vj = 0.f;
                uint4 d = __ldg(x4 + (size_t)cj * 16 + slot);
                float2 f0 = __half22float2(*reinterpret_cast<__half2*>(&d.x));
                float2 f1 = __half22float2(*reinterpret_cast<__half2*>(&d.y));
                float2 f2 = __half22float2(*reinterpret_cast<__half2*>(&d.z));
                float2 f3 = __half22float2(*reinterpret_cast<__half2*>(&d.w));
                a[0] += vj * f0.x; a[1] += vj * f0.y;
                a[2] += vj * f1.x; a[3] += vj * f1.y;
                a[4] += vj * f2.x; a[5] += vj * f2.y;
                a[6] += vj * f3.x; a[7] += vj * f3.y;
            }
        }
    }
    #pragma unroll
    for (int q = 0; q < 8; q++)
        a[q] += __shfl_xor_sync(0xffffffffu, a[q], 16);
}

// ---------------- phase-1 SpMM: fp16 output -----------------------------------
__device__ __forceinline__ void spmm_h_job(const int*  __restrict__ rowptr,
                                           const int2* __restrict__ edge,
                                           const __half* __restrict__ x,
                                           __half* __restrict__ yout,
                                           int nrows, int bid) {
    const int lane = threadIdx.x & 31;
    const int half16 = lane >> 4;
    const int slot = lane & 15;
    const int row  = bid * 8 + ((int)threadIdx.x >> 5);
    if (row >= nrows) return;
    float a[8];
    spmm_accum(rowptr, edge, x, row, lane, half16, slot, a);
    if (lane < 16) {
        __half2 h0 = __floats2half2_rn(a[0], a[1]);
        __half2 h1 = __floats2half2_rn(a[2], a[3]);
        __half2 h2 = __floats2half2_rn(a[4], a[5]);
        __half2 h3 = __floats2half2_rn(a[6], a[7]);
        uint4 o;
        o.x = *reinterpret_cast<unsigned int*>(&h0);
        o.y = *reinterpret_cast<unsigned int*>(&h1);
        o.z = *reinterpret_cast<unsigned int*>(&h2);
        o.w = *reinterpret_cast<unsigned int*>(&h3);
        reinterpret_cast<uint4*>(yout)[(size_t)row * 16 + slot] = o;
    }
}

__global__ void spmm_h_dual(const int*  __restrict__ ptrA, const int2* __restrict__ edgeA,
                            const __half* __restrict__ xA, __half* __restrict__ yA,
                            int nA, int blocksA,
                            const int*  __restrict__ ptrB, const int2* __restrict__ edgeB,
                            const __half* __restrict__ xB, __half* __restrict__ yB,
                            int nB) {
    if ((int)blockIdx.x < blocksA)
        spmm_h_job(ptrA, edgeA, xA, yA, nA, blockIdx.x);
    else
        spmm_h_job(ptrB, edgeB, xB, yB, nB, blockIdx.x - blocksA);
}

// ---------------- phase-3+4 fused: SpMM -> LN -> leaky -> feat+=, acc update --
__device__ __forceinline__ void spmm_ln_job(const int*  __restrict__ rowptr,
                                            const int2* __restrict__ edge,
                                            const __half* __restrict__ x,
                                            const float* __restrict__ g,
                                            const float* __restrict__ b,
                                            __half* __restrict__ feat,
                                            float* __restrict__ acc,
                                            int nrows, int bid, float oscale) {
    const int lane = threadIdx.x & 31;
    const int half16 = lane >> 4;
    const int slot = lane & 15;
    const int row  = bid * 8 + ((int)threadIdx.x >> 5);
    if (row >= nrows) return;
    float a[8];
    spmm_accum(rowptr, edge, x, row, lane, half16, slot, a);

    float s = 0.f, q = 0.f;
    #pragma unroll
    for (int t = 0; t < 8; t++) { s += a[t]; q += a[t] * a[t]; }
    #pragma unroll
    for (int off = 8; off; off >>= 1) {
        s += __shfl_xor_sync(0xffffffffu, s, off);
        q += __shfl_xor_sync(0xffffffffu, q, off);
    }
    const float inv = 1.f / (float)D_H;
    float mu = s * inv;
    float rs = rsqrtf(q * inv - mu * mu + EPS_F);

    if (lane < 16) {
        const float4 g0 = __ldg(reinterpret_cast<const float4*>(g) + 2 * slot);
        const float4 g1 = __ldg(reinterpret_cast<const float4*>(g) + 2 * slot + 1);
        const float4 b0 = __ldg(reinterpret_cast<const float4*>(b) + 2 * slot);
        const float4 b1 = __ldg(reinterpret_cast<const float4*>(b) + 2 * slot + 1);
        float h[8];
        h[0] = leakyf((a[0] - mu) * rs * g0.x + b0.x);
        h[1] = leakyf((a[1] - mu) * rs * g0.y + b0.y);
        h[2] = leakyf((a[2] - mu) * rs * g0.z + b0.z);
        h[3] = leakyf((a[3] - mu) * rs * g0.w + b0.w);
        h[4] = leakyf((a[4] - mu) * rs * g1.x + b1.x);
        h[5] = leakyf((a[5] - mu) * rs * g1.y + b1.y);
        h[6] = leakyf((a[6] - mu) * rs * g1.z + b1.z);
        h[7] = leakyf((a[7] - mu) * rs * g1.w + b1.w);
        uint4* fp = reinterpret_cast<uint4*>(feat) + (size_t)row * 16 + slot;
        uint4 fd = *fp;
        float2 f0 = __half22float2(*reinterpret_cast<__half2*>(&fd.x));
        float2 f1 = __half22float2(*reinterpret_cast<__half2*>(&fd.y));
        float2 f2 = __half22float2(*reinterpret_cast<__half2*>(&fd.z));
        float2 f3 = __half22float2(*reinterpret_cast<__half2*>(&fd.w));
        __half2 o0 = __floats2half2_rn(f0.x + h[0], f0.y + h[1]);
        __half2 o1 = __floats2half2_rn(f1.x + h[2], f1.y + h[3]);
        __half2 o2 = __floats2half2_rn(f2.x + h[4], f2.y + h[5]);
        __half2 o3 = __floats2half2_rn(f3.x + h[6], f3.y + h[7]);
        fd.x = *reinterpret_cast<unsigned int*>(&o0);
        fd.y = *reinterpret_cast<unsigned int*>(&o1);
        fd.z = *reinterpret_cast<unsigned int*>(&o2);
        fd.w = *reinterpret_cast<unsigned int*>(&o3);
        *fp = fd;
        float4* ap = reinterpret_cast<float4*>(acc) + (size_t)row * 32 + 2 * slot;
        float4 av0 = ap[0];
        float4 av1 = ap[1];
        av0.x = (av0.x + h[0]) * oscale;
        av0.y = (av0.y + h[1]) * oscale;
        av0.z = (av0.z + h[2]) * oscale;
        av0.w = (av0.w + h[3]) * oscale;
        av1.x = (av1.x + h[4]) * oscale;
        av1.y = (av1.y + h[5]) * oscale;
        av1.z = (av1.z + h[6]) * oscale;
        av1.w = (av1.w + h[7]) * oscale;
        ap[0] = av0;
        ap[1] = av1;
    }
}

__global__ void spmm_ln_dual(const int*  __restrict__ ptrA, const int2* __restrict__ edgeA,
                             const __half* __restrict__ xA,
                             const float* __restrict__ gA, const float* __restrict__ bA,
                             __half* __restrict__ featA, float* __restrict__ accA,
                             int nA, int blocksA,
                             const int*  __restrict__ ptrB, const int2* __restrict__ edgeB,
                             const __half* __restrict__ xB,
                             const float* __restrict__ gB, const float* __restrict__ bB,
                             __half* __restrict__ featB, float* __restrict__ accB,
                             int nB, float oscale) {
    if ((int)blockIdx.x < blocksA)
        spmm_ln_job(ptrA, edgeA, xA, gA, bA, featA, accA, nA, blockIdx.x, oscale);
    else
        spmm_ln_job(ptrB, edgeB, xB, gB, bB, featB, accB, nB, blockIdx.x - blocksA, oscale);
}

// ---------------- tensor-core GEMM (X @ W^T) + LayerNorm ---------------------
// Block: 128 threads (4 warps). M-tile = 16 rows; warp w owns cols [32w,32w+32).
__device__ __forceinline__ void gemm_ln_mma_job(const __half* __restrict__ X,
                                                const __half* __restrict__ Wt,
                                                const float* __restrict__ g,
                                                const float* __restrict__ b,
                                                __half* __restrict__ out,
                                                int nrows, int bid, int nblocks,
                                                __half* sW, __half* sX) {
    const int tid  = threadIdx.x;
    const int w    = tid >> 5;
    const int lane = tid & 31;

    __shared__ float sSum[16][4];
    __shared__ float sSq [16][4];
    __shared__ float sMu [16];
    __shared__ float sRs [16];

    {
        const uint4* src = reinterpret_cast<const uint4*>(Wt);
        uint4* dst = reinterpret_cast<uint4*>(sW);
        const int n16 = D_H * WPITCH / 8;
        for (int i = tid; i < n16; i += 128) dst[i] = src[i];
    }
    __syncthreads();

    unsigned int bfr[8][4][2];
    {
        unsigned int swBase = (unsigned int)__cvta_generic_to_shared(sW);
        #pragma unroll
        for (int kc = 0; kc < 8; kc++) {
            #pragma unroll
            for (int ncl = 0; ncl < 4; ncl++) {
                int krow = kc * 16 + (lane & 15);
                int col  = w * 32 + ncl * 8;
                unsigned int addr = swBase + (unsigned int)((krow * WPITCH + col) * 2);
                asm volatile("ldmatrix.sync.aligned.m8n8.x2.trans.shared.b16 {%0,%1}, [%2];"
                             : "=r"(bfr[kc][ncl][0]), "=r"(bfr[kc][ncl][1]) : "r"(addr));
            }
        }
    }

    float2 gv[4], bv[4];
    #pragma unroll
    for (int ncl = 0; ncl < 4; ncl++) {
        int j = w * 32 + ncl * 8 + (lane & 3) * 2;
        gv[ncl] = *reinterpret_cast<const float2*>(g + j);
        bv[ncl] = *reinterpret_cast<const float2*>(b + j);
    }

    const int ntiles = (nrows + 15) >> 4;
    unsigned int sxBase = (unsigned int)__cvta_generic_to_shared(sX);

    for (int tile = bid; tile < ntiles; tile += nblocks) {
        const int rowbase = tile * 16;
        {
            int r = tid >> 3;            // 0..15
            int p = tid & 7;             // 0..7, two uint4 chunks each
            int grow = rowbase + r;
            uint4 z = make_uint4(0, 0, 0, 0);
            const uint4* xr = reinterpret_cast<const uint4*>(X) + (size_t)grow * 16;
            uint4* dst = reinterpret_cast<uint4*>(sX + r * WPITCH);
            if (grow < nrows) {
                dst[p]     = __ldg(xr + p);
                dst[p + 8] = __ldg(xr + p + 8);
            } else {
                dst[p] = z; dst[p + 8] = z;
            }
        }
        __syncthreads();

        float acc[4][4];
        #pragma unroll
        for (int ncl = 0; ncl < 4; ncl++)
            #pragma unroll
            for (int q = 0; q < 4; q++) acc[ncl][q] = 0.f;

        #pragma unroll
        for (int kc = 0; kc < 8; kc++) {
            unsigned int a0, a1, a2, a3;
            int arow = (lane & 7) + ((lane >> 3) & 1) * 8;
            int acol = kc * 16 + ((lane >> 4) & 1) * 8;
            unsigned int addr = sxBase + (unsigned int)((arow * WPITCH + acol) * 2);
            asm volatile("ldmatrix.sync.aligned.m8n8.x4.shared.b16 {%0,%1,%2,%3}, [%4];"
                         : "=r"(a0), "=r"(a1), "=r"(a2), "=r"(a3) : "r"(addr));
            #pragma unroll
            for (int ncl = 0; ncl < 4; ncl++) {
                asm volatile("mma.sync.aligned.m16n8k16.row.col.f32.f16.f16.f32 "
                             "{%0,%1,%2,%3}, {%4,%5,%6,%7}, {%8,%9}, {%0,%1,%2,%3};"
                             : "+f"(acc[ncl][0]), "+f"(acc[ncl][1]),
                               "+f"(acc[ncl][2]), "+f"(acc[ncl][3])
                             : "r"(a0), "r"(a1), "r"(a2), "r"(a3),
                               "r"(bfr[kc][ncl][0]), "r"(bfr[kc][ncl][1]));
            }
        }

        float s0 = 0.f, s1 = 0.f, q0 = 0.f, q1 = 0.f;
        #pragma unroll
        for (int ncl = 0; ncl < 4; ncl++) {
            s0 += acc[ncl][0] + acc[ncl][1];
            s1 += acc[ncl][2] + acc[ncl][3];
            q0 += acc[ncl][0] * acc[ncl][0] + acc[ncl][1] * acc[ncl][1];
            q1 += acc[ncl][2] * acc[ncl][2] + acc[ncl][3] * acc[ncl][3];
        }
        s0 += __shfl_xor_sync(0xffffffffu, s0, 1);
        s0 += __shfl_xor_sync(0xffffffffu, s0, 2);
        s1 += __shfl_xor_sync(0xffffffffu, s1, 1);
        s1 += __shfl_xor_sync(0xffffffffu, s1, 2);
        q0 += __shfl_xor_sync(0xffffffffu, q0, 1);
        q0 += __shfl_xor_sync(0xffffffffu, q0, 2);
        q1 += __shfl_xor_sync(0xffffffffu, q1, 1);
        q1 += __shfl_xor_sync(0xffffffffu, q1, 2);
        if ((lane & 3) == 0) {
            int r = lane >> 2;
            sSum[r][w] = s0; sSum[r + 8][w] = s1;
            sSq [r][w] = q0; sSq [r + 8][w] = q1;
        }
        __syncthreads();
        if (tid < 16) {
            float s = sSum[tid][0] + sSum[tid][1] + sSum[tid][2] + sSum[tid][3];
            float q = sSq[tid][0] + sSq[tid][1] + sSq[tid][2] + sSq[tid][3];
            float mu = s * (1.f / 128.f);
            float var = q * (1.f / 128.f) - mu * mu;
            sMu[tid] = mu;
            sRs[tid] = rsqrtf(var + EPS_F);
        }
        __syncthreads();

        {
            int r0 = lane >> 2;
            float mu0 = sMu[r0],     rs0 = sRs[r0];
            float mu1 = sMu[r0 + 8], rs1 = sRs[r0 + 8];
            int grow0 = rowbase + r0;
            int grow1 = rowbase + r0 + 8;
            #pragma unroll
            for (int ncl = 0; ncl < 4; ncl++) {
                int j = w * 32 + ncl * 8 + (lane & 3) * 2;
                if (grow0 < nrows) {
                    __half2 o = __floats2half2_rn(
                        (acc[ncl][0] - mu0) * rs0 * gv[ncl].x + bv[ncl].x,
                        (acc[ncl][1] - mu0) * rs0 * gv[ncl].y + bv[ncl].y);
                    *reinterpret_cast<__half2*>(out + (size_t)grow0 * D_H + j) = o;
                }
                if (grow1 < nrows) {
                    __half2 o = __floats2half2_rn(
                        (acc[ncl][2] - mu1) * rs1 * gv[ncl].x + bv[ncl].x,
                        (acc[ncl][3] - mu1) * rs1 * gv[ncl].y + bv[ncl].y);
                    *reinterpret_cast<__half2*>(out + (size_t)grow1 * D_H + j) = o;
                }
            }
        }
        __syncthreads();
    }
}

__global__ void gemm_ln_mma_dual(const __half* __restrict__ XA, const __half* __restrict__ WtA,
                                 const float* __restrict__ gA, const float* __restrict__ bA,
                                 __half* __restrict__ outA, int nA, int blocksA,
                                 const __half* __restrict__ XB, const __half* __restrict__ WtB,
                                 const float* __restrict__ gB, const float* __restrict__ bB,
                                 __half* __restrict__ outB, int nB, int blocksB) {
    extern __shared__ __half smem[];
    __half* sW = smem;                       // D_H * WPITCH halfs
    __half* sX = smem + D_H * WPITCH;        // 16 * WPITCH halfs
    if ((int)blockIdx.x < blocksA)
        gemm_ln_mma_job(XA, WtA, gA, bA, outA, nA, blockIdx.x, blocksA, sW, sX);
    else
        gemm_ln_mma_job(XB, WtB, gB, bB, outB, nB, blockIdx.x - blocksA, blocksB, sW, sX);
}

// ---------------- launch ------------------------------------------------------
extern "C" void kernel_launch(void* const* d_in, const int* in_sizes, int n_in,
                              void* d_out, int out_size) {
    const float* emb     = (const float*)d_in[0];
    const float* fc_u_w  = (const float*)d_in[1];
    const float* fc_u_b  = (const float*)d_in[2];
    const float* fc_i_w  = (const float*)d_in[3];
    const float* fc_i_b  = (const float*)d_in[4];
    const float* vals    = (const float*)d_in[5];
    const float* Wu      = (const float*)d_in[6];
    const float* ln1g_u  = (const float*)d_in[7];
    const float* ln1b_u  = (const float*)d_in[8];
    const float* ln2g_u  = (const float*)d_in[9];
    const float* ln2b_u  = (const float*)d_in[10];
    const float* Wi      = (const float*)d_in[11];
    const float* ln1g_i  = (const float*)d_in[12];
    const float* ln1b_i  = (const float*)d_in[13];
    const float* ln2g_i  = (const float*)d_in[14];
    const float* ln2b_i  = (const float*)d_in[15];
    const int*   rows    = (const int*)d_in[16];
    const int*   cols    = (const int*)d_in[17];
    float* out = (float*)d_out;
    const int nnz = in_sizes[5];
    (void)n_in; (void)out_size;

    __half *hU, *hI, *xhU, *xhI, *lU, *lI, *Wt0;
    int *ptrU, *ptrI, *posU, *posI, *cntU, *cntI, *chU, *chI;
    int2 *edgeU, *edgeI;
    cudaGetSymbolAddress((void**)&hU, g_hU);
    cudaGetSymbolAddress((void**)&hI, g_hI);
    cudaGetSymbolAddress((void**)&xhU, g_xhU);
    cudaGetSymbolAddress((void**)&xhI, g_xhI);
    cudaGetSymbolAddress((void**)&lU, g_lU);
    cudaGetSymbolAddress((void**)&lI, g_lI);
    cudaGetSymbolAddress((void**)&Wt0, g_Wt);
    cudaGetSymbolAddress((void**)&ptrU, g_ptrU);
    cudaGetSymbolAddress((void**)&ptrI, g_ptrI);
    cudaGetSymbolAddress((void**)&posU, g_posU);
    cudaGetSymbolAddress((void**)&posI, g_posI);
    cudaGetSymbolAddress((void**)&cntU, g_cntU);
    cudaGetSymbolAddress((void**)&cntI, g_cntI);
    cudaGetSymbolAddress((void**)&chU, g_chunkU);
    cudaGetSymbolAddress((void**)&chI, g_chunkI);
    cudaGetSymbolAddress((void**)&edgeU, g_edgeU);
    cudaGetSymbolAddress((void**)&edgeI, g_edgeI);

    const int EB = (nnz + 255) / 256;
    const int NCHU = (N_U + CHUNK - 1) / CHUNK;
    const int NCHI = (N_I + CHUNK - 1) / CHUNK;
    const size_t GEMM_SMEM = (size_t)(D_H + 16) * WPITCH * sizeof(__half);

    float* accU = out;
    float* accI = out + (size_t)N_U * D_H;

    // -------- prep: zero counters; then hist || fc_u || fc_i || wconvert -----
    zero_int2arr<<<256, 256>>>(cntU, N_U, cntI, N_I);
    prep_fused<<<HB + FU + FI + WC, 128>>>(rows, cols, cntU, cntI, nnz,
                                           emb, fc_u_w, fc_u_b, fc_i_w, fc_i_b,
                                           hU, hI, accU, accI, Wu, Wi);

    // -------- scan + build --------
    scan_reduce_dual<<<NCHU + NCHI, 256>>>(cntU, chU, NCHU, cntI, chI);
    scan_write_dual<<<NCHU + NCHI, CHUNK>>>(cntU, chU, ptrU, posU, NCHU,
                                            cntI, chI, ptrI, posI);
    build_both_kernel<<<EB, 256>>>(rows, cols, vals, posU, posI, edgeU, edgeI, nnz);

    const int SPU = (N_U + 7) / 8;
    const int SPI = (N_I + 7) / 8;
    const int GA = 512, GB = 1024;

    for (int k = 0; k < N_LAYERS; k++) {
        const __half* WtU_k = Wt0 + (size_t)k * WPITCH * D_H;
        const __half* WtI_k = Wt0 + (size_t)(2 + k) * WPITCH * D_H;
        const float oscale = (k == N_LAYERS - 1) ? (1.f / 3.f) : 1.f;

        // phase 1: xhI = A^T u  ||  xhU = A i   [fp16 out]
        spmm_h_dual<<<SPI + SPU, 256>>>(ptrI, edgeI, hU, xhI, N_I, SPI,
                                        ptrU, edgeU, hI, xhU, N_U);
        // phase 2: lI = LN(xhI Wu^T)  ||  lU = LN(xhU Wi^T)  [tensor cores]
        gemm_ln_mma_dual<<<GA + GB, 128, GEMM_SMEM>>>(
            xhI, WtU_k, ln1g_u + k * D_H, ln1b_u + k * D_H, lI, N_I, GA,
            xhU, WtI_k, ln1g_i + k * D_H, ln1b_i + k * D_H, lU, N_U, GB);
        // phase 3+4 fused: u-update from A lI  ||  i-update from A^T lU
        spmm_ln_dual<<<SPU + SPI, 256>>>(ptrU, edgeU, lI,
                                         ln2g_u + k * D_H, ln2b_u + k * D_H,
                                         hU, accU, N_U, SPU,
                                         ptrI, edgeI, lU,
                                         ln2g_i + k * D_H, ln2b_i + k * D_H,
                                         hI, accI, N_I, oscale);
    }
}